// round 13
// baseline (speedup 1.0000x reference)
#include <cuda_runtime.h>
#include <cstdint>

#define NN 100000
#define RR 3
#define EE 800000
#define LL 200000

// ---------------- scratch ----------------
// fp16 tables: 32 f16x2 words per node row
__device__ __align__(16) unsigned g_agg_h[(size_t)2 * RR * NN * 32];
__device__ __align__(16) unsigned g_xh[(size_t)NN * 32];    // x in fp16
__device__ __align__(16) unsigned g_mixh[(size_t)NN * 32];  // mix in fp16
__device__ __align__(16) float g_z[(size_t)NN * 2];
__device__ float g_score[6];   // [layer*3 + r]

// fp16 weight fragments, PAIRED uint4 layout, per layer 6656 uint4:
//  [0,3072):   REL|ROOT pairs: r*1024 + (j*4+ks)*32 + lane -> {Fr.x,Fr.y,Fo.x,Fo.y}
//  [3072,6144): GRU pairs, gate-major: m*1024 + (j*4+ks)*32 + lane -> {Fi.x,Fi.y,Fh.x,Fh.y}
//  [6144,6656): ATT ks-pairs: (j*2+kp)*32 + lane -> {F(2kp).x,.y, F(2kp+1).x,.y}
#define WL4 6656
__device__ __align__(16) uint4 g_wfrag[2 * WL4];

// SMEM layout (uint4 units): relroot slice 1024, gru 3072, att 512
#define S_GRU 1024
#define S_ATT 4096
#define SM_TOTAL (4608 * 16)   // 73728 B

// ---------------- fp16 helpers ----------------
__device__ __forceinline__ unsigned pack_h2(float x, float y) {   // lo=x, hi=y
    unsigned d;
    asm("cvt.rn.f16x2.f32 %0, %1, %2;" : "=r"(d) : "f"(y), "f"(x));
    return d;
}
__device__ __forceinline__ void mma_h(float* d, const unsigned* a, unsigned b0, unsigned b1) {
    asm volatile(
        "mma.sync.aligned.m16n8k16.row.col.f32.f16.f16.f32 "
        "{%0,%1,%2,%3},{%4,%5,%6,%7},{%8,%9},{%0,%1,%2,%3};"
        : "+f"(d[0]), "+f"(d[1]), "+f"(d[2]), "+f"(d[3])
        : "r"(a[0]), "r"(a[1]), "r"(a[2]), "r"(a[3]), "r"(b0), "r"(b1));
}
// load one fragment (4 words) from a packed fp16 table row pair
__device__ __forceinline__ void load_frag16(const unsigned* tbl, int nA, int nB, int ks, int t,
                                            unsigned* f) {
    int w0 = ks * 8 + t;
    f[0] = tbl[(size_t)nA * 32 + w0];
    f[1] = tbl[(size_t)nB * 32 + w0];
    f[2] = tbl[(size_t)nA * 32 + w0 + 4];
    f[3] = tbl[(size_t)nB * 32 + w0 + 4];
}
// load + convert one fragment from fp32 [*, 64] matrix (single fp16)
__device__ __forceinline__ void load_frag32(const float* base, int nA, int nB, int k0,
                                            unsigned* f) {
    float2 v;
    v = *(const float2*)(base + (size_t)nA * 64 + k0);      f[0] = pack_h2(v.x, v.y);
    v = *(const float2*)(base + (size_t)nB * 64 + k0);      f[1] = pack_h2(v.x, v.y);
    v = *(const float2*)(base + (size_t)nA * 64 + k0 + 8);  f[2] = pack_h2(v.x, v.y);
    v = *(const float2*)(base + (size_t)nB * 64 + k0 + 8);  f[3] = pack_h2(v.x, v.y);
}

// ---------------- presplit: build paired uint4 fragment tables ----------------
__global__ void k_presplit(
    const float* __restrict__ w1rel, const float* __restrict__ w1root,
    const float* __restrict__ wi1, const float* __restrict__ wh1,
    const float* __restrict__ kw1,
    const float* __restrict__ w2rel, const float* __restrict__ w2root,
    const float* __restrict__ wi2, const float* __restrict__ wh2,
    const float* __restrict__ kw2) {
    int f = blockIdx.x * blockDim.x + threadIdx.x;
    if (f >= 2 * WL4) return;
    int l = f / WL4;
    int fo = f - l * WL4;
    uint4 out;
    if (fo < 3072) {
        int r = fo >> 10, rem = fo & 1023;
        int j = rem >> 7, ks = (rem >> 5) & 3, lane = rem & 31;
        int g = lane >> 2, t = lane & 3;
        const float* Wr = (l ? w2rel : w1rel) + (size_t)(r * 64 + j * 8 + g) * 64;
        const float* Wo = (l ? w2root : w1root) + (size_t)(r * 64 + j * 8 + g) * 64;
        int k0 = ks * 16 + 2 * t;
        out = make_uint4(pack_h2(Wr[k0], Wr[k0 + 1]), pack_h2(Wr[k0 + 8], Wr[k0 + 9]),
                         pack_h2(Wo[k0], Wo[k0 + 1]), pack_h2(Wo[k0 + 8], Wo[k0 + 9]));
    } else if (fo < 6144) {
        int q = fo - 3072;
        int m = q >> 10, rem = q & 1023;
        int j = rem >> 7, ks = (rem >> 5) & 3, lane = rem & 31;
        int g = lane >> 2, t = lane & 3;
        const float* Wi = (l ? wi2 : wi1) + (size_t)(m * 64 + j * 8 + g) * 64;
        const float* Wh = (l ? wh2 : wh1) + (size_t)(m * 64 + j * 8 + g) * 64;
        int k0 = ks * 16 + 2 * t;
        out = make_uint4(pack_h2(Wi[k0], Wi[k0 + 1]), pack_h2(Wi[k0 + 8], Wi[k0 + 9]),
                         pack_h2(Wh[k0], Wh[k0 + 1]), pack_h2(Wh[k0 + 8], Wh[k0 + 9]));
    } else {
        int q = fo - 6144;
        int j = q >> 6, kp = (q >> 5) & 1, lane = q & 31;
        int g = lane >> 2, t = lane & 3;
        const float* K = (l ? kw2 : kw1) + (size_t)(j * 8 + g) * 64;
        int ka = (2 * kp) * 16 + 2 * t, kb2 = ka + 16;
        out = make_uint4(pack_h2(K[ka], K[ka + 1]), pack_h2(K[ka + 8], K[ka + 9]),
                         pack_h2(K[kb2], K[kb2 + 1]), pack_h2(K[kb2 + 8], K[kb2 + 9]));
    }
    g_wfrag[f] = out;
}

// ---------------- zero agg (fp16) + convert x -> fp16 + zero scores ----------------
__global__ void k_zeroall(const float* __restrict__ x) {
    int i = blockIdx.x * blockDim.x + threadIdx.x;
    const int totz = 2 * RR * NN * 8;   // uint4 count of g_agg_h
    if (i < totz) ((uint4*)g_agg_h)[i] = make_uint4(0u, 0u, 0u, 0u);
    if (i < NN * 8) {
        const float4* p = (const float4*)(x + (size_t)i * 8);
        float4 v0 = p[0], v1 = p[1];
        ((uint4*)g_xh)[i] = make_uint4(pack_h2(v0.x, v0.y), pack_h2(v0.z, v0.w),
                                       pack_h2(v1.x, v1.y), pack_h2(v1.z, v1.w));
    }
    if (i < 6) g_score[i] = 0.f;
}

// ---------------- scatter: agg[layer][r][dst] += feat16[src], red.v4.f16x2 ----------------
__global__ void k_scatter(int layer, const int* __restrict__ ei) {
    unsigned idx = blockIdx.x * blockDim.x + threadIdx.x;
    if (idx >= (unsigned)RR * EE * 8u) return;
    const unsigned* src = layer ? g_mixh : g_xh;
    unsigned chunk = idx & 7u;
    unsigned e = idx >> 3;
    unsigned r = e / EE;
    unsigned eo = e - r * EE;
    int s = ei[(size_t)r * 2 * EE + eo];
    int d = ei[(size_t)r * 2 * EE + EE + eo];
    uint4 v = *(const uint4*)(src + (size_t)s * 32 + chunk * 4);
    unsigned* o = g_agg_h + ((size_t)((size_t)layer * RR + r) * NN + d) * 32 + chunk * 4;
    asm volatile("red.global.add.noftz.v4.f16x2 [%0], {%1, %2, %3, %4};"
                 :: "l"(o), "r"(v.x), "r"(v.y), "r"(v.z), "r"(v.w) : "memory");
}

// ---------------- GRU epilogue ----------------
__device__ __forceinline__ float gru_out(float gi_r, float gi_z, float gi_n,
                                         float gh_r, float gh_z, float gh_n, float p) {
    float rg = 1.f / (1.f + __expf(-(gi_r + gh_r)));
    float zg = 1.f / (1.f + __expf(-(gi_z + gh_z)));
    float ng = tanhf(gi_n + rg * gh_n);
    return (1.f - zg) * ng + zg * p;
}

// ---------------- fused layer: conv -> GRU -> attention score ----------------
__global__ __launch_bounds__(256, 2) void k_layer(
    int layer,
    const float* __restrict__ past,
    const float* __restrict__ brel,
    const float* __restrict__ bi, const float* __restrict__ bh,
    const float* __restrict__ kb, const float* __restrict__ q,
    float* __restrict__ cur) {
    extern __shared__ uint4 sW4[];   // 4608 uint4
    const int r = blockIdx.y, tid = threadIdx.x;
    const int lane = tid & 31, warp = tid >> 5;
    const int g = lane >> 2, t = lane & 3;
    const int rowA = blockIdx.x * 128 + warp * 16 + g;
    const int rowB = rowA + 8;
    const int nA = min(rowA, NN - 1), nB = min(rowB, NN - 1);
    const unsigned* Ab16 = g_agg_h + (size_t)((size_t)layer * RR + r) * NN * 32;
    const unsigned* Rb16 = layer ? g_mixh : g_xh;
    const float* Pbase = past + (size_t)r * NN * 64;

    // ---- cooperative copy of this r's weight fragments into SMEM ----
    {
        const uint4* wb = g_wfrag + layer * WL4;
        for (int i = tid; i < 4608; i += 256) {
            const uint4* s;
            if (i < 1024)      s = wb + r * 1024 + i;
            else if (i < 4096) s = wb + 3072 + (i - 1024);
            else               s = wb + 6144 + (i - 4096);
            sW4[i] = *s;
        }
    }
    __syncthreads();

    unsigned Hh[16];   // conv output fragments (registers, lane-private repack)

    // ===== phase A: graphconv -> Hh =====
    {
        unsigned Ah[16], Rh[16];
#pragma unroll
        for (int ks = 0; ks < 4; ks++) {
            load_frag16(Ab16, nA, nB, ks, t, Ah + ks * 4);
            load_frag16(Rb16, nA, nB, ks, t, Rh + ks * 4);
        }
#pragma unroll
        for (int j = 0; j < 8; j++) {
            float acc0[4] = {}, acc1[4] = {};
#pragma unroll
            for (int ks = 0; ks < 4; ks++) {
                uint4 F = sW4[(j * 4 + ks) * 32 + lane];
                float* acc = (ks & 1) ? acc1 : acc0;
                mma_h(acc, Ah + ks * 4, F.x, F.y);
                mma_h(acc, Rh + ks * 4, F.z, F.w);
            }
            int c0 = j * 8 + 2 * t;
            float2 bb = *(const float2*)(brel + r * 64 + c0);
            float o0 = fmaxf(acc0[0] + acc1[0] + bb.x, 0.f);
            float o1 = fmaxf(acc0[1] + acc1[1] + bb.y, 0.f);
            float o2 = fmaxf(acc0[2] + acc1[2] + bb.x, 0.f);
            float o3 = fmaxf(acc0[3] + acc1[3] + bb.y, 0.f);
            int slot = (j >> 1) * 4 + ((j & 1) ? 2 : 0);
            Hh[slot] = pack_h2(o0, o1);
            Hh[slot + 1] = pack_h2(o2, o3);
        }
    }

    unsigned Ch[16];   // GRU output fragments

    // ===== phase B: GRU =====
    {
        unsigned Ph[16];
#pragma unroll
        for (int ks = 0; ks < 4; ks++)
            load_frag32(Pbase, nA, nB, ks * 16 + 2 * t, Ph + ks * 4);
#pragma unroll
        for (int j = 0; j < 8; j++) {
            float acc[6][4] = {};
#pragma unroll
            for (int ks = 0; ks < 4; ks++) {
#pragma unroll
                for (int m = 0; m < 3; m++) {
                    uint4 F = sW4[S_GRU + m * 1024 + (j * 4 + ks) * 32 + lane];
                    mma_h(acc[m],     Hh + ks * 4, F.x, F.y);
                    mma_h(acc[3 + m], Ph + ks * 4, F.z, F.w);
                }
            }
            int c0 = j * 8 + 2 * t;
            float2 bir = *(const float2*)(bi + c0);
            float2 biz = *(const float2*)(bi + 64 + c0);
            float2 bin = *(const float2*)(bi + 128 + c0);
            float2 bhr = *(const float2*)(bh + c0);
            float2 bhz = *(const float2*)(bh + 64 + c0);
            float2 bhn = *(const float2*)(bh + 128 + c0);
            float2 pA = *(const float2*)(Pbase + (size_t)nA * 64 + c0);
            float2 pB = *(const float2*)(Pbase + (size_t)nB * 64 + c0);
            float o0 = gru_out(acc[0][0] + bir.x, acc[1][0] + biz.x, acc[2][0] + bin.x,
                               acc[3][0] + bhr.x, acc[4][0] + bhz.x, acc[5][0] + bhn.x, pA.x);
            float o1 = gru_out(acc[0][1] + bir.y, acc[1][1] + biz.y, acc[2][1] + bin.y,
                               acc[3][1] + bhr.y, acc[4][1] + bhz.y, acc[5][1] + bhn.y, pA.y);
            float o2 = gru_out(acc[0][2] + bir.x, acc[1][2] + biz.x, acc[2][2] + bin.x,
                               acc[3][2] + bhr.x, acc[4][2] + bhz.x, acc[5][2] + bhn.x, pB.x);
            float o3 = gru_out(acc[0][3] + bir.y, acc[1][3] + biz.y, acc[2][3] + bin.y,
                               acc[3][3] + bhr.y, acc[4][3] + bhz.y, acc[5][3] + bhn.y, pB.y);
            if (rowA < NN) *(float2*)(cur + ((size_t)r * NN + rowA) * 64 + c0) = make_float2(o0, o1);
            if (rowB < NN) *(float2*)(cur + ((size_t)r * NN + rowB) * 64 + c0) = make_float2(o2, o3);
            int slot = (j >> 1) * 4 + ((j & 1) ? 2 : 0);
            Ch[slot] = pack_h2(o0, o1);
            Ch[slot + 1] = pack_h2(o2, o3);
        }
    }

    // ===== phase C: attention score =====
    {
        float ssum = 0.f;
#pragma unroll
        for (int j = 0; j < 8; j++) {
            float accA[4] = {}, accB[4] = {};
#pragma unroll
            for (int kp = 0; kp < 2; kp++) {
                uint4 F = sW4[S_ATT + (j * 2 + kp) * 32 + lane];
                mma_h(accA, Ch + (2 * kp) * 4, F.x, F.y);
                mma_h(accB, Ch + (2 * kp + 1) * 4, F.z, F.w);
            }
            int c0 = j * 8 + 2 * t;
            float2 kbv = *(const float2*)(kb + c0);
            float2 qv  = *(const float2*)(q + c0);
            if (rowA < NN)
                ssum += qv.x * tanhf(accA[0] + accB[0] + kbv.x)
                      + qv.y * tanhf(accA[1] + accB[1] + kbv.y);
            if (rowB < NN)
                ssum += qv.x * tanhf(accA[2] + accB[2] + kbv.x)
                      + qv.y * tanhf(accA[3] + accB[3] + kbv.y);
        }
#pragma unroll
        for (int o = 16; o; o >>= 1) ssum += __shfl_down_sync(0xffffffffu, ssum, o);
        if (lane == 0) atomicAdd(&g_score[layer * 3 + r], ssum);
    }
}

// ---------------- softmax helper (inline, per thread) ----------------
__device__ __forceinline__ void softmax3(int layer, float& a0, float& a1, float& a2) {
    const float inv = 1.0f / (float)NN;
    float s0 = g_score[layer * 3 + 0] * inv;
    float s1 = g_score[layer * 3 + 1] * inv;
    float s2 = g_score[layer * 3 + 2] * inv;
    float m = fmaxf(s0, fmaxf(s1, s2));
    float e0 = __expf(s0 - m), e1 = __expf(s1 - m), e2 = __expf(s2 - m);
    float d = 1.f / (e0 + e1 + e2);
    a0 = e0 * d; a1 = e1 * d; a2 = e2 * d;
}

// ---------------- attention mix (softmax fused): fp16 output ----------------
__global__ void k_mix(const float* __restrict__ cur) {
    int i = blockIdx.x * blockDim.x + threadIdx.x;
    if (i >= NN * 16) return;
    float a0, a1, a2;
    softmax3(0, a0, a1, a2);
    const float4* c = (const float4*)cur;
    float4 v0 = c[i], v1 = c[i + (size_t)NN * 16], v2 = c[i + (size_t)2 * NN * 16];
    float ox = a0 * v0.x + a1 * v1.x + a2 * v2.x;
    float oy = a0 * v0.y + a1 * v1.y + a2 * v2.y;
    float oz = a0 * v0.z + a1 * v1.z + a2 * v2.z;
    float ow = a0 * v0.w + a1 * v1.w + a2 * v2.w;
    *(uint2*)(g_mixh + (size_t)i * 2) = make_uint2(pack_h2(ox, oy), pack_h2(oz, ow));
}

// ---------------- final projection (softmax fused) ----------------
__global__ __launch_bounds__(128) void k_zfuse(
    const float* __restrict__ cur2, const float* __restrict__ postW,
    const float* __restrict__ postb) {
    int node = blockIdx.x * blockDim.x + threadIdx.x;
    if (node >= NN) return;
    float a0, a1, a2;
    softmax3(1, a0, a1, a2);
    const float4* c0 = (const float4*)(cur2 + (size_t)node * 64);
    const float4* c1 = (const float4*)(cur2 + ((size_t)NN + node) * 64);
    const float4* c2 = (const float4*)(cur2 + ((size_t)2 * NN + node) * 64);
    const float4* w0 = (const float4*)postW;
    const float4* w1 = (const float4*)(postW + 64);
    float z0 = postb[0], z1 = postb[1];
#pragma unroll
    for (int i = 0; i < 16; i++) {
        float4 u0 = c0[i], u1 = c1[i], u2 = c2[i];
        float4 m;
        m.x = a0 * u0.x + a1 * u1.x + a2 * u2.x;
        m.y = a0 * u0.y + a1 * u1.y + a2 * u2.y;
        m.z = a0 * u0.z + a1 * u1.z + a2 * u2.z;
        m.w = a0 * u0.w + a1 * u1.w + a2 * u2.w;
        float4 p0 = w0[i], p1 = w1[i];
        z0 += m.x * p0.x + m.y * p0.y + m.z * p0.z + m.w * p0.w;
        z1 += m.x * p1.x + m.y * p1.y + m.z * p1.z + m.w * p1.w;
    }
    g_z[2 * node] = z0;
    g_z[2 * node + 1] = z1;
}

// ---------------- link scores ----------------
__global__ void k_score(const int* __restrict__ eli, const float* __restrict__ rel,
                        float* __restrict__ scores) {
    int idx = blockIdx.x * blockDim.x + threadIdx.x;
    if (idx >= RR * LL) return;
    int r = idx / LL;
    int l = idx - r * LL;
    int hd = eli[(size_t)r * 2 * LL + l];
    int tl = eli[(size_t)r * 2 * LL + LL + l];
    float hr = g_z[2 * hd], hi = g_z[2 * hd + 1];
    float tr = g_z[2 * tl], ti = g_z[2 * tl + 1];
    float rr = rel[2 * r], ri = rel[2 * r + 1];
    scores[idx] = hr * rr * tr + hi * rr * ti + hr * ri * ti - hi * ri * tr;
}

// ---------------- host ----------------
extern "C" void kernel_launch(void* const* d_in, const int* in_sizes, int n_in,
                              void* d_out, int out_size) {
    const float* x      = (const float*)d_in[0];
    const int*   ei     = (const int*)d_in[1];
    const int*   eli    = (const int*)d_in[2];
    const float* past1  = (const float*)d_in[3];
    const float* past2  = (const float*)d_in[4];
    const float* W1rel  = (const float*)d_in[5];
    const float* b1rel  = (const float*)d_in[6];
    const float* W1root = (const float*)d_in[7];
    const float* g1Wi   = (const float*)d_in[8];
    const float* g1Wh   = (const float*)d_in[9];
    const float* g1bi   = (const float*)d_in[10];
    const float* g1bh   = (const float*)d_in[11];
    const float* k1W    = (const float*)d_in[12];
    const float* k1b    = (const float*)d_in[13];
    const float* q1     = (const float*)d_in[14];
    const float* W2rel  = (const float*)d_in[15];
    const float* b2rel  = (const float*)d_in[16];
    const float* W2root = (const float*)d_in[17];
    const float* g2Wi   = (const float*)d_in[18];
    const float* g2Wh   = (const float*)d_in[19];
    const float* g2bi   = (const float*)d_in[20];
    const float* g2bh   = (const float*)d_in[21];
    const float* k2W    = (const float*)d_in[22];
    const float* k2b    = (const float*)d_in[23];
    const float* q2     = (const float*)d_in[24];
    const float* postW  = (const float*)d_in[25];
    const float* postb  = (const float*)d_in[26];
    const float* relemb = (const float*)d_in[27];

    float* out    = (float*)d_out;
    float* scores = out;
    float* cur1   = out + (size_t)RR * LL;
    float* cur2   = cur1 + (size_t)RR * NN * 64;

    cudaFuncSetAttribute(k_layer, cudaFuncAttributeMaxDynamicSharedMemorySize, SM_TOTAL);

    dim3 gridL((NN + 127) / 128, RR);   // 782 x 3
    const int scat_blocks = (RR * EE * 8 + 255) / 256;

    k_zeroall<<<(2 * RR * NN * 8 + 255) / 256, 256>>>(x);
    k_presplit<<<(2 * WL4 + 255) / 256, 256>>>(
        W1rel, W1root, g1Wi, g1Wh, k1W, W2rel, W2root, g2Wi, g2Wh, k2W);
    k_scatter<<<scat_blocks, 256>>>(0, ei);
    k_layer<<<gridL, 256, SM_TOTAL>>>(0, past1, b1rel, g1bi, g1bh, k1b, q1, cur1);
    k_mix<<<(NN * 16 + 255) / 256, 256>>>(cur1);
    k_scatter<<<scat_blocks, 256>>>(1, ei);   // profiled launch (-s 5 -c 1)
    k_layer<<<gridL, 256, SM_TOTAL>>>(1, past2, b2rel, g2bi, g2bh, k2b, q2, cur2);
    k_zfuse<<<(NN + 127) / 128, 128>>>(cur2, postW, postb);
    k_score<<<(RR * LL + 255) / 256, 256>>>(eli, relemb, scores);
}

// round 14
// speedup vs baseline: 1.2112x; 1.2112x over previous
#include <cuda_runtime.h>
#include <cstdint>

#define NN 100000
#define RR 3
#define EE 800000
#define LL 200000

// ---------------- scratch ----------------
// fp16 tables: 32 f16x2 words per node row, PERMUTED layout:
//   pos = t*8 + ks*2 + half  <->  orig word w = ks*8 + half*4 + t   (t=0..3, ks=0..3, half=0..1)
__device__ __align__(16) unsigned g_agg_h[(size_t)2 * RR * NN * 32];
__device__ __align__(16) unsigned g_xh[(size_t)NN * 32];    // x in fp16 (permuted)
__device__ __align__(16) unsigned g_mixh[(size_t)NN * 32];  // mix in fp16 (permuted)
__device__ __align__(16) float g_z[(size_t)NN * 2];
__device__ float g_score[6];   // [layer*3 + r]

// fp16 weight fragments, MMA B-fragment order (uint2 = 8 B per lane-frag)
#define WF_REL  0
#define WF_ROOT 3072
#define WF_WI   6144
#define WF_WH   9216
#define WF_ATT  12288
#define WF_LAYER 13312
__device__ __align__(16) uint2 g_wfrag[2 * WF_LAYER];

// SMEM weight slice offsets (uint2 units): rel, root (r-slices), wi, wh, att
#define SREL  0
#define SROOT 1024
#define SWI   2048
#define SWH   5120
#define SATT  8192
#define SW_U2 9216                 // 73728 bytes
#define STROW 36
#define WSTW  576                  // stage words per warp (16 rows x 36)
#define SM_TOTAL (SW_U2 * 8 + 8 * WSTW * 4)   // 73728 + 18432 = 92160 B

// ---------------- fast math ----------------
__device__ __forceinline__ float tanh_fast(float x) {
    float y;
    asm("tanh.approx.f32 %0, %1;" : "=f"(y) : "f"(x));
    return y;
}
__device__ __forceinline__ float sigmoid_fast(float x) {
    float e = __expf(-x);
    float y;
    asm("rcp.approx.f32 %0, %1;" : "=f"(y) : "f"(1.0f + e));
    return y;
}

// ---------------- fp16 helpers ----------------
__device__ __forceinline__ unsigned pack_h2(float x, float y) {   // lo=x, hi=y
    unsigned d;
    asm("cvt.rn.f16x2.f32 %0, %1, %2;" : "=r"(d) : "f"(y), "f"(x));
    return d;
}
__device__ __forceinline__ void mma_h(float* d, const unsigned* a, unsigned b0, unsigned b1) {
    asm volatile(
        "mma.sync.aligned.m16n8k16.row.col.f32.f16.f16.f32 "
        "{%0,%1,%2,%3},{%4,%5,%6,%7},{%8,%9},{%0,%1,%2,%3};"
        : "+f"(d[0]), "+f"(d[1]), "+f"(d[2]), "+f"(d[3])
        : "r"(a[0]), "r"(a[1]), "r"(a[2]), "r"(a[3]), "r"(b0), "r"(b1));
}
// load all 4 ks-fragments (16 words) from PERMUTED fp16 table rows nA/nB: 4 x LDG.128
__device__ __forceinline__ void load_tile_perm(const unsigned* tbl, int nA, int nB, int t,
                                               unsigned* f) {
    const uint4* ra = (const uint4*)(tbl + (size_t)nA * 32) + t * 2;
    const uint4* rb = (const uint4*)(tbl + (size_t)nB * 32) + t * 2;
    uint4 a0 = ra[0], a1 = ra[1];
    uint4 b0 = rb[0], b1 = rb[1];
    f[0] = a0.x;  f[2] = a0.y;  f[4] = a0.z;  f[6] = a0.w;
    f[8] = a1.x;  f[10] = a1.y; f[12] = a1.z; f[14] = a1.w;
    f[1] = b0.x;  f[3] = b0.y;  f[5] = b0.z;  f[7] = b0.w;
    f[9] = b1.x;  f[11] = b1.y; f[13] = b1.z; f[15] = b1.w;
}
// load + convert one fragment from fp32 [*, 64] matrix (single fp16)
__device__ __forceinline__ void load_frag32(const float* base, int nA, int nB, int k0,
                                            unsigned* f) {
    float2 v;
    v = *(const float2*)(base + (size_t)nA * 64 + k0);      f[0] = pack_h2(v.x, v.y);
    v = *(const float2*)(base + (size_t)nB * 64 + k0);      f[1] = pack_h2(v.x, v.y);
    v = *(const float2*)(base + (size_t)nA * 64 + k0 + 8);  f[2] = pack_h2(v.x, v.y);
    v = *(const float2*)(base + (size_t)nB * 64 + k0 + 8);  f[3] = pack_h2(v.x, v.y);
}

// ---------------- presplit ALL weights (both layers) to fp16 fragments ----------------
__global__ void k_presplit(
    const float* __restrict__ w1rel, const float* __restrict__ w1root,
    const float* __restrict__ wi1, const float* __restrict__ wh1,
    const float* __restrict__ kw1,
    const float* __restrict__ w2rel, const float* __restrict__ w2root,
    const float* __restrict__ wi2, const float* __restrict__ wh2,
    const float* __restrict__ kw2) {
    int f = blockIdx.x * blockDim.x + threadIdx.x;
    if (f >= 2 * WF_LAYER) return;
    int l = f / WF_LAYER;
    int fo = f - l * WF_LAYER;
    const float* W;
    int fl;
    if (fo < 3072)       { W = l ? w2rel : w1rel;   fl = fo; }
    else if (fo < 6144)  { W = l ? w2root : w1root; fl = fo - 3072; }
    else if (fo < 9216)  { W = l ? wi2 : wi1;       fl = fo - 6144; }
    else if (fo < 12288) { W = l ? wh2 : wh1;       fl = fo - 9216; }
    else                 { W = l ? kw2 : kw1;       fl = fo - 12288; }
    int lane = fl & 31;
    int ks = (fl >> 5) & 3;
    int j = fl >> 7;
    int g = lane >> 2, t = lane & 3;
    const float* row = W + (size_t)(j * 8 + g) * 64;
    int k0 = ks * 16 + 2 * t;
    g_wfrag[f] = make_uint2(pack_h2(row[k0], row[k0 + 1]),
                            pack_h2(row[k0 + 8], row[k0 + 9]));
}

// ---------------- zero agg (fp16) + convert x -> permuted fp16 + zero scores ----------------
__global__ void k_zeroall(const float* __restrict__ x) {
    int i = blockIdx.x * blockDim.x + threadIdx.x;
    const int totz = 2 * RR * NN * 8;   // uint4 count of g_agg_h
    if (i < totz) ((uint4*)g_agg_h)[i] = make_uint4(0u, 0u, 0u, 0u);
    if (i < NN * 8) {
        int node = i >> 3, gq = i & 7;
        const float* row = x + (size_t)node * 64;
        unsigned w[4];
#pragma unroll
        for (int u = 0; u < 4; u++) {
            int p = gq * 4 + u;
            int t = p >> 3, ks = (p >> 1) & 3, half = p & 1;
            int wo = ks * 8 + half * 4 + t;
            float2 v = *(const float2*)(row + 2 * wo);
            w[u] = pack_h2(v.x, v.y);
        }
        ((uint4*)g_xh)[i] = make_uint4(w[0], w[1], w[2], w[3]);
    }
    if (i < 6) g_score[i] = 0.f;
}

// ---------------- scatter: agg[layer][r][dst] += feat16[src], red.v4.f16x2 ----------------
// (row layout is permuted; scatter is a row-copy so it is permutation-invariant)
__global__ void k_scatter(int layer, const int* __restrict__ ei) {
    unsigned idx = blockIdx.x * blockDim.x + threadIdx.x;
    if (idx >= (unsigned)RR * EE * 8u) return;
    const unsigned* src = layer ? g_mixh : g_xh;
    unsigned chunk = idx & 7u;
    unsigned e = idx >> 3;
    unsigned r = e / EE;
    unsigned eo = e - r * EE;
    int s = ei[(size_t)r * 2 * EE + eo];
    int d = ei[(size_t)r * 2 * EE + EE + eo];
    uint4 v = *(const uint4*)(src + (size_t)s * 32 + chunk * 4);
    unsigned* o = g_agg_h + ((size_t)((size_t)layer * RR + r) * NN + d) * 32 + chunk * 4;
    asm volatile("red.global.add.noftz.v4.f16x2 [%0], {%1, %2, %3, %4};"
                 :: "l"(o), "r"(v.x), "r"(v.y), "r"(v.z), "r"(v.w) : "memory");
}

// ---------------- fused layer: conv -> GRU -> attention score ----------------
__global__ __launch_bounds__(256, 2) void k_layer(
    int layer,
    const float* __restrict__ past,
    const float* __restrict__ brel,
    const float* __restrict__ bi, const float* __restrict__ bh,
    const float* __restrict__ kb, const float* __restrict__ q,
    float* __restrict__ cur) {
    extern __shared__ char smem[];
    uint2* sW = (uint2*)smem;                                  // 9216 uint2 weight slices
    unsigned* stage = (unsigned*)(smem + SW_U2 * 8);           // 8 x 576 words
    const int r = blockIdx.y, tid = threadIdx.x;
    const int lane = tid & 31, warp = tid >> 5;
    const int g = lane >> 2, t = lane & 3;
    const int rowA = blockIdx.x * 128 + warp * 16 + g;
    const int rowB = rowA + 8;
    const int nA = min(rowA, NN - 1), nB = min(rowB, NN - 1);
    const unsigned* Ab16 = g_agg_h + (size_t)((size_t)layer * RR + r) * NN * 32;
    const unsigned* Rb16 = layer ? g_mixh : g_xh;
    const float* Pbase = past + (size_t)r * NN * 64;
    unsigned* st = stage + warp * WSTW;

    // ---- cooperative copy of this r's weight fragments into SMEM ----
    {
        const uint2* wb = g_wfrag + layer * WF_LAYER;
        uint4* sW4 = (uint4*)sW;
        for (int i = tid; i < 4608; i += 256) {
            const uint4* s;
            if (i < 512)       s = (const uint4*)(wb + WF_REL + r * 1024) + i;
            else if (i < 1024) s = (const uint4*)(wb + WF_ROOT + r * 1024) + (i - 512);
            else if (i < 2560) s = (const uint4*)(wb + WF_WI) + (i - 1024);
            else if (i < 4096) s = (const uint4*)(wb + WF_WH) + (i - 2560);
            else               s = (const uint4*)(wb + WF_ATT) + (i - 4096);
            sW4[i] = *s;
        }
    }
    __syncthreads();

    // ===== phase A: graphconv -> H (fp16) into stage =====
    {
        unsigned Ah[16], Rh[16];
        load_tile_perm(Ab16, nA, nB, t, Ah);
        load_tile_perm(Rb16, nA, nB, t, Rh);
#pragma unroll
        for (int j = 0; j < 8; j++) {
            float acc0[4] = {}, acc1[4] = {};
#pragma unroll
            for (int ks = 0; ks < 4; ks++) {
                uint2 Fr = sW[SREL + ((j * 4 + ks) << 5) + lane];
                uint2 Fo = sW[SROOT + ((j * 4 + ks) << 5) + lane];
                mma_h(acc0, Ah + ks * 4, Fr.x, Fr.y);
                mma_h(acc1, Rh + ks * 4, Fo.x, Fo.y);
            }
            int c0 = j * 8 + 2 * t;
            float2 bb = *(const float2*)(brel + r * 64 + c0);
            int wj = j * 4 + t;
            st[g * STROW + wj] = pack_h2(fmaxf(acc0[0] + acc1[0] + bb.x, 0.f),
                                         fmaxf(acc0[1] + acc1[1] + bb.y, 0.f));
            st[(g + 8) * STROW + wj] = pack_h2(fmaxf(acc0[2] + acc1[2] + bb.x, 0.f),
                                               fmaxf(acc0[3] + acc1[3] + bb.y, 0.f));
        }
    }
    __syncwarp();

    // ===== phase B: GRU; H from stage, past from global; C -> stage =====
    {
        unsigned Hh[16], Ph[16];
#pragma unroll
        for (int ks = 0; ks < 4; ks++) {
            int w0 = ks * 8 + t;
            Hh[ks * 4 + 0] = st[g * STROW + w0];
            Hh[ks * 4 + 1] = st[(g + 8) * STROW + w0];
            Hh[ks * 4 + 2] = st[g * STROW + w0 + 4];
            Hh[ks * 4 + 3] = st[(g + 8) * STROW + w0 + 4];
            load_frag32(Pbase, nA, nB, ks * 16 + 2 * t, Ph + ks * 4);
        }
        __syncwarp();
#pragma unroll
        for (int j = 0; j < 8; j++) {
            // fused accumulators: [0]=r(i+h), [1]=z(i+h), [2]=in, [3]=hn
            float acc[4][4] = {};
#pragma unroll
            for (int ks = 0; ks < 4; ks++) {
                uint2 Fir = sW[SWI + (((0 * 8 + j) * 4 + ks) << 5) + lane];
                uint2 Fhr = sW[SWH + (((0 * 8 + j) * 4 + ks) << 5) + lane];
                mma_h(acc[0], Hh + ks * 4, Fir.x, Fir.y);
                mma_h(acc[0], Ph + ks * 4, Fhr.x, Fhr.y);
                uint2 Fiz = sW[SWI + (((1 * 8 + j) * 4 + ks) << 5) + lane];
                uint2 Fhz = sW[SWH + (((1 * 8 + j) * 4 + ks) << 5) + lane];
                mma_h(acc[1], Hh + ks * 4, Fiz.x, Fiz.y);
                mma_h(acc[1], Ph + ks * 4, Fhz.x, Fhz.y);
                uint2 Fin = sW[SWI + (((2 * 8 + j) * 4 + ks) << 5) + lane];
                uint2 Fhn = sW[SWH + (((2 * 8 + j) * 4 + ks) << 5) + lane];
                mma_h(acc[2], Hh + ks * 4, Fin.x, Fin.y);
                mma_h(acc[3], Ph + ks * 4, Fhn.x, Fhn.y);
            }
            int c0 = j * 8 + 2 * t;
            float2 bir = *(const float2*)(bi + c0);
            float2 biz = *(const float2*)(bi + 64 + c0);
            float2 bin = *(const float2*)(bi + 128 + c0);
            float2 bhr = *(const float2*)(bh + c0);
            float2 bhz = *(const float2*)(bh + 64 + c0);
            float2 bhn = *(const float2*)(bh + 128 + c0);
            float brx = bir.x + bhr.x, bry = bir.y + bhr.y;
            float bzx = biz.x + bhz.x, bzy = biz.y + bhz.y;
            float2 pA = *(const float2*)(Pbase + (size_t)nA * 64 + c0);
            float2 pB = *(const float2*)(Pbase + (size_t)nB * 64 + c0);
            float o[4];
#pragma unroll
            for (int e = 0; e < 4; e++) {
                float bx = (e & 1) ? bry : brx;
                float bz = (e & 1) ? bzy : bzx;
                float bn_i = (e & 1) ? bin.y : bin.x;
                float bn_h = (e & 1) ? bhn.y : bhn.x;
                float p = (e & 2) ? ((e & 1) ? pB.y : pB.x) : ((e & 1) ? pA.y : pA.x);
                float rg = sigmoid_fast(acc[0][e] + bx);
                float zg = sigmoid_fast(acc[1][e] + bz);
                float ng = tanh_fast(acc[2][e] + bn_i + rg * (acc[3][e] + bn_h));
                o[e] = (1.f - zg) * ng + zg * p;
            }
            if (rowA < NN) *(float2*)(cur + ((size_t)r * NN + rowA) * 64 + c0) = make_float2(o[0], o[1]);
            if (rowB < NN) *(float2*)(cur + ((size_t)r * NN + rowB) * 64 + c0) = make_float2(o[2], o[3]);
            int wj = j * 4 + t;
            st[g * STROW + wj] = pack_h2(o[0], o[1]);
            st[(g + 8) * STROW + wj] = pack_h2(o[2], o[3]);
        }
    }
    __syncwarp();

    // ===== phase C: attention score; C from stage (2-way accumulator ILP) =====
    {
        unsigned Ch[16];
#pragma unroll
        for (int ks = 0; ks < 4; ks++) {
            int w0 = ks * 8 + t;
            Ch[ks * 4 + 0] = st[g * STROW + w0];
            Ch[ks * 4 + 1] = st[(g + 8) * STROW + w0];
            Ch[ks * 4 + 2] = st[g * STROW + w0 + 4];
            Ch[ks * 4 + 3] = st[(g + 8) * STROW + w0 + 4];
        }
        float ssum = 0.f;
#pragma unroll
        for (int j = 0; j < 8; j++) {
            float accA[4] = {}, accB[4] = {};
#pragma unroll
            for (int ks = 0; ks < 4; ks++) {
                uint2 F = sW[SATT + ((j * 4 + ks) << 5) + lane];
                mma_h((ks & 1) ? accB : accA, Ch + ks * 4, F.x, F.y);
            }
            int c0 = j * 8 + 2 * t;
            float2 kbv = *(const float2*)(kb + c0);
            float2 qv  = *(const float2*)(q + c0);
            if (rowA < NN)
                ssum += qv.x * tanh_fast(accA[0] + accB[0] + kbv.x)
                      + qv.y * tanh_fast(accA[1] + accB[1] + kbv.y);
            if (rowB < NN)
                ssum += qv.x * tanh_fast(accA[2] + accB[2] + kbv.x)
                      + qv.y * tanh_fast(accA[3] + accB[3] + kbv.y);
        }
#pragma unroll
        for (int o = 16; o; o >>= 1) ssum += __shfl_down_sync(0xffffffffu, ssum, o);
        if (lane == 0) atomicAdd(&g_score[layer * 3 + r], ssum);
    }
}

// ---------------- softmax helper (inline, per thread) ----------------
__device__ __forceinline__ void softmax3(int layer, float& a0, float& a1, float& a2) {
    const float inv = 1.0f / (float)NN;
    float s0 = g_score[layer * 3 + 0] * inv;
    float s1 = g_score[layer * 3 + 1] * inv;
    float s2 = g_score[layer * 3 + 2] * inv;
    float m = fmaxf(s0, fmaxf(s1, s2));
    float e0 = __expf(s0 - m), e1 = __expf(s1 - m), e2 = __expf(s2 - m);
    float d = 1.f / (e0 + e1 + e2);
    a0 = e0 * d; a1 = e1 * d; a2 = e2 * d;
}

// ---------------- attention mix (softmax fused): permuted fp16 output ----------------
__global__ void k_mix(const float* __restrict__ cur) {
    int i = blockIdx.x * blockDim.x + threadIdx.x;
    if (i >= NN * 8) return;
    float a0, a1, a2;
    softmax3(0, a0, a1, a2);
    int node = i >> 3, gq = i & 7;
    const float* c0 = cur + (size_t)node * 64;
    const float* c1 = c0 + (size_t)NN * 64;
    const float* c2 = c1 + (size_t)NN * 64;
    unsigned w[4];
#pragma unroll
    for (int u = 0; u < 4; u++) {
        int p = gq * 4 + u;
        int t = p >> 3, ks = (p >> 1) & 3, half = p & 1;
        int col = 2 * (ks * 8 + half * 4 + t);
        float2 v0 = *(const float2*)(c0 + col);
        float2 v1 = *(const float2*)(c1 + col);
        float2 v2 = *(const float2*)(c2 + col);
        w[u] = pack_h2(a0 * v0.x + a1 * v1.x + a2 * v2.x,
                       a0 * v0.y + a1 * v1.y + a2 * v2.y);
    }
    ((uint4*)g_mixh)[i] = make_uint4(w[0], w[1], w[2], w[3]);
}

// ---------------- final projection (softmax fused) ----------------
__global__ __launch_bounds__(128) void k_zfuse(
    const float* __restrict__ cur2, const float* __restrict__ postW,
    const float* __restrict__ postb) {
    int node = blockIdx.x * blockDim.x + threadIdx.x;
    if (node >= NN) return;
    float a0, a1, a2;
    softmax3(1, a0, a1, a2);
    const float4* c0 = (const float4*)(cur2 + (size_t)node * 64);
    const float4* c1 = (const float4*)(cur2 + ((size_t)NN + node) * 64);
    const float4* c2 = (const float4*)(cur2 + ((size_t)2 * NN + node) * 64);
    const float4* w0 = (const float4*)postW;
    const float4* w1 = (const float4*)(postW + 64);
    float z0 = postb[0], z1 = postb[1];
#pragma unroll
    for (int i = 0; i < 16; i++) {
        float4 u0 = c0[i], u1 = c1[i], u2 = c2[i];
        float4 m;
        m.x = a0 * u0.x + a1 * u1.x + a2 * u2.x;
        m.y = a0 * u0.y + a1 * u1.y + a2 * u2.y;
        m.z = a0 * u0.z + a1 * u1.z + a2 * u2.z;
        m.w = a0 * u0.w + a1 * u1.w + a2 * u2.w;
        float4 p0 = w0[i], p1 = w1[i];
        z0 += m.x * p0.x + m.y * p0.y + m.z * p0.z + m.w * p0.w;
        z1 += m.x * p1.x + m.y * p1.y + m.z * p1.z + m.w * p1.w;
    }
    g_z[2 * node] = z0;
    g_z[2 * node + 1] = z1;
}

// ---------------- link scores ----------------
__global__ void k_score(const int* __restrict__ eli, const float* __restrict__ rel,
                        float* __restrict__ scores) {
    int idx = blockIdx.x * blockDim.x + threadIdx.x;
    if (idx >= RR * LL) return;
    int r = idx / LL;
    int l = idx - r * LL;
    int hd = eli[(size_t)r * 2 * LL + l];
    int tl = eli[(size_t)r * 2 * LL + LL + l];
    float hr = g_z[2 * hd], hi = g_z[2 * hd + 1];
    float tr = g_z[2 * tl], ti = g_z[2 * tl + 1];
    float rr = rel[2 * r], ri = rel[2 * r + 1];
    scores[idx] = hr * rr * tr + hi * rr * ti + hr * ri * ti - hi * ri * tr;
}

// ---------------- host ----------------
extern "C" void kernel_launch(void* const* d_in, const int* in_sizes, int n_in,
                              void* d_out, int out_size) {
    const float* x      = (const float*)d_in[0];
    const int*   ei     = (const int*)d_in[1];
    const int*   eli    = (const int*)d_in[2];
    const float* past1  = (const float*)d_in[3];
    const float* past2  = (const float*)d_in[4];
    const float* W1rel  = (const float*)d_in[5];
    const float* b1rel  = (const float*)d_in[6];
    const float* W1root = (const float*)d_in[7];
    const float* g1Wi   = (const float*)d_in[8];
    const float* g1Wh   = (const float*)d_in[9];
    const float* g1bi   = (const float*)d_in[10];
    const float* g1bh   = (const float*)d_in[11];
    const float* k1W    = (const float*)d_in[12];
    const float* k1b    = (const float*)d_in[13];
    const float* q1     = (const float*)d_in[14];
    const float* W2rel  = (const float*)d_in[15];
    const float* b2rel  = (const float*)d_in[16];
    const float* W2root = (const float*)d_in[17];
    const float* g2Wi   = (const float*)d_in[18];
    const float* g2Wh   = (const float*)d_in[19];
    const float* g2bi   = (const float*)d_in[20];
    const float* g2bh   = (const float*)d_in[21];
    const float* k2W    = (const float*)d_in[22];
    const float* k2b    = (const float*)d_in[23];
    const float* q2     = (const float*)d_in[24];
    const float* postW  = (const float*)d_in[25];
    const float* postb  = (const float*)d_in[26];
    const float* relemb = (const float*)d_in[27];

    float* out    = (float*)d_out;
    float* scores = out;
    float* cur1   = out + (size_t)RR * LL;
    float* cur2   = cur1 + (size_t)RR * NN * 64;

    cudaFuncSetAttribute(k_layer, cudaFuncAttributeMaxDynamicSharedMemorySize, SM_TOTAL);

    dim3 gridL((NN + 127) / 128, RR);   // 782 x 3
    const int scat_blocks = (RR * EE * 8 + 255) / 256;

    k_zeroall<<<(2 * RR * NN * 8 + 255) / 256, 256>>>(x);
    k_presplit<<<(2 * WF_LAYER + 255) / 256, 256>>>(
        W1rel, W1root, g1Wi, g1Wh, k1W, W2rel, W2root, g2Wi, g2Wh, k2W);
    k_scatter<<<scat_blocks, 256>>>(0, ei);
    k_layer<<<gridL, 256, SM_TOTAL>>>(0, past1, b1rel, g1bi, g1bh, k1b, q1, cur1);
    k_mix<<<(NN * 8 + 255) / 256, 256>>>(cur1);
    k_scatter<<<scat_blocks, 256>>>(1, ei);   // profiled launch (-s 5 -c 1)
    k_layer<<<gridL, 256, SM_TOTAL>>>(1, past2, b2rel, g2bi, g2bh, k2b, q2, cur2);
    k_zfuse<<<(NN + 127) / 128, 128>>>(cur2, postW, postb);
    k_score<<<(RR * LL + 255) / 256, 256>>>(eli, relemb, scores);
}

// round 15
// speedup vs baseline: 1.2495x; 1.0317x over previous
#include <cuda_runtime.h>
#include <cstdint>

#define NN 100000
#define RR 3
#define EE 800000
#define LL 200000

// ---------------- scratch ----------------
// fp16 tables: 32 f16x2 words per node row, PERMUTED layout:
//   pos = t*8 + ks*2 + half  <->  orig word w = ks*8 + half*4 + t
__device__ __align__(16) unsigned g_agg_h[(size_t)2 * RR * NN * 32];
__device__ __align__(16) unsigned g_xh[(size_t)NN * 32];    // x in fp16 (permuted)
__device__ __align__(16) unsigned g_mixh[(size_t)NN * 32];  // mix in fp16 (permuted)
__device__ __align__(16) float g_z[(size_t)NN * 2];
__device__ float g_score[6];   // [layer*3 + r]

// fp16 weight fragments, PAIRED uint4 layout, per layer WL4 uint4:
//  [0,3072):    REL|ROOT pairs:  r*1024 + (j*4+ks)*32 + lane -> {Fr.x,Fr.y,Fo.x,Fo.y}
//  [3072,6144): GRU pairs (gate-major): m*1024 + (j*4+ks)*32 + lane -> {Fi.x,Fi.y,Fh.x,Fh.y}
//  [6144,6656): ATT ks-pairs: (j*2+kp)*32 + lane -> {F(2kp).x,.y, F(2kp+1).x,.y}
#define WL4 6656
__device__ __align__(16) uint4 g_wfrag[2 * WL4];

// SMEM (uint4 units): conv slice 1024 @0, gru 3072 @1024, att 512 @4096; then stage
#define S_GRU 1024
#define S_ATT 4096
#define SW_U4 4608                 // 73728 bytes of weights
#define STROW 36
#define WSTW  576                  // stage words per warp (16 rows x 36)
#define SM_TOTAL (SW_U4 * 16 + 8 * WSTW * 4)   // 73728 + 18432 = 92160 B

// ---------------- fast math ----------------
__device__ __forceinline__ float tanh_fast(float x) {
    float y;
    asm("tanh.approx.f32 %0, %1;" : "=f"(y) : "f"(x));
    return y;
}
__device__ __forceinline__ float sigmoid_fast(float x) {
    float e = __expf(-x);
    float y;
    asm("rcp.approx.f32 %0, %1;" : "=f"(y) : "f"(1.0f + e));
    return y;
}

// ---------------- fp16 helpers ----------------
__device__ __forceinline__ unsigned pack_h2(float x, float y) {   // lo=x, hi=y
    unsigned d;
    asm("cvt.rn.f16x2.f32 %0, %1, %2;" : "=r"(d) : "f"(y), "f"(x));
    return d;
}
__device__ __forceinline__ void mma_h(float* d, const unsigned* a, unsigned b0, unsigned b1) {
    asm volatile(
        "mma.sync.aligned.m16n8k16.row.col.f32.f16.f16.f32 "
        "{%0,%1,%2,%3},{%4,%5,%6,%7},{%8,%9},{%0,%1,%2,%3};"
        : "+f"(d[0]), "+f"(d[1]), "+f"(d[2]), "+f"(d[3])
        : "r"(a[0]), "r"(a[1]), "r"(a[2]), "r"(a[3]), "r"(b0), "r"(b1));
}
// load all 4 ks-fragments (16 words) from PERMUTED fp16 table rows nA/nB: 4 x LDG.128
__device__ __forceinline__ void load_tile_perm(const unsigned* tbl, int nA, int nB, int t,
                                               unsigned* f) {
    const uint4* ra = (const uint4*)(tbl + (size_t)nA * 32) + t * 2;
    const uint4* rb = (const uint4*)(tbl + (size_t)nB * 32) + t * 2;
    uint4 a0 = ra[0], a1 = ra[1];
    uint4 b0 = rb[0], b1 = rb[1];
    f[0] = a0.x;  f[2] = a0.y;  f[4] = a0.z;  f[6] = a0.w;
    f[8] = a1.x;  f[10] = a1.y; f[12] = a1.z; f[14] = a1.w;
    f[1] = b0.x;  f[3] = b0.y;  f[5] = b0.z;  f[7] = b0.w;
    f[9] = b1.x;  f[11] = b1.y; f[13] = b1.z; f[15] = b1.w;
}
// load + convert one fragment from fp32 [*, 64] matrix (single fp16)
__device__ __forceinline__ void load_frag32(const float* base, int nA, int nB, int k0,
                                            unsigned* f) {
    float2 v;
    v = *(const float2*)(base + (size_t)nA * 64 + k0);      f[0] = pack_h2(v.x, v.y);
    v = *(const float2*)(base + (size_t)nB * 64 + k0);      f[1] = pack_h2(v.x, v.y);
    v = *(const float2*)(base + (size_t)nA * 64 + k0 + 8);  f[2] = pack_h2(v.x, v.y);
    v = *(const float2*)(base + (size_t)nB * 64 + k0 + 8);  f[3] = pack_h2(v.x, v.y);
}

// ---------------- presplit: build paired uint4 fragment tables ----------------
__global__ void k_presplit(
    const float* __restrict__ w1rel, const float* __restrict__ w1root,
    const float* __restrict__ wi1, const float* __restrict__ wh1,
    const float* __restrict__ kw1,
    const float* __restrict__ w2rel, const float* __restrict__ w2root,
    const float* __restrict__ wi2, const float* __restrict__ wh2,
    const float* __restrict__ kw2) {
    int f = blockIdx.x * blockDim.x + threadIdx.x;
    if (f >= 2 * WL4) return;
    int l = f / WL4;
    int fo = f - l * WL4;
    uint4 out;
    if (fo < 3072) {
        int r = fo >> 10, rem = fo & 1023;
        int j = rem >> 7, ks = (rem >> 5) & 3, lane = rem & 31;
        int g = lane >> 2, t = lane & 3;
        const float* Wr = (l ? w2rel : w1rel) + (size_t)(r * 64 + j * 8 + g) * 64;
        const float* Wo = (l ? w2root : w1root) + (size_t)(r * 64 + j * 8 + g) * 64;
        int k0 = ks * 16 + 2 * t;
        out = make_uint4(pack_h2(Wr[k0], Wr[k0 + 1]), pack_h2(Wr[k0 + 8], Wr[k0 + 9]),
                         pack_h2(Wo[k0], Wo[k0 + 1]), pack_h2(Wo[k0 + 8], Wo[k0 + 9]));
    } else if (fo < 6144) {
        int qq = fo - 3072;
        int m = qq >> 10, rem = qq & 1023;
        int j = rem >> 7, ks = (rem >> 5) & 3, lane = rem & 31;
        int g = lane >> 2, t = lane & 3;
        const float* Wi = (l ? wi2 : wi1) + (size_t)(m * 64 + j * 8 + g) * 64;
        const float* Wh = (l ? wh2 : wh1) + (size_t)(m * 64 + j * 8 + g) * 64;
        int k0 = ks * 16 + 2 * t;
        out = make_uint4(pack_h2(Wi[k0], Wi[k0 + 1]), pack_h2(Wi[k0 + 8], Wi[k0 + 9]),
                         pack_h2(Wh[k0], Wh[k0 + 1]), pack_h2(Wh[k0 + 8], Wh[k0 + 9]));
    } else {
        int qq = fo - 6144;
        int j = qq >> 6, kp = (qq >> 5) & 1, lane = qq & 31;
        int g = lane >> 2, t = lane & 3;
        const float* K = (l ? kw2 : kw1) + (size_t)(j * 8 + g) * 64;
        int ka = (2 * kp) * 16 + 2 * t, kb2 = ka + 16;
        out = make_uint4(pack_h2(K[ka], K[ka + 1]), pack_h2(K[ka + 8], K[ka + 9]),
                         pack_h2(K[kb2], K[kb2 + 1]), pack_h2(K[kb2 + 8], K[kb2 + 9]));
    }
    g_wfrag[f] = out;
}

// ---------------- zero agg (fp16) + convert x -> permuted fp16 + zero scores ----------------
__global__ void k_zeroall(const float* __restrict__ x) {
    int i = blockIdx.x * blockDim.x + threadIdx.x;
    const int totz = 2 * RR * NN * 8;   // uint4 count of g_agg_h
    if (i < totz) ((uint4*)g_agg_h)[i] = make_uint4(0u, 0u, 0u, 0u);
    if (i < NN * 8) {
        int node = i >> 3, gq = i & 7;
        const float* row = x + (size_t)node * 64;
        unsigned w[4];
#pragma unroll
        for (int u = 0; u < 4; u++) {
            int p = gq * 4 + u;
            int t = p >> 3, ks = (p >> 1) & 3, half = p & 1;
            int wo = ks * 8 + half * 4 + t;
            float2 v = *(const float2*)(row + 2 * wo);
            w[u] = pack_h2(v.x, v.y);
        }
        ((uint4*)g_xh)[i] = make_uint4(w[0], w[1], w[2], w[3]);
    }
    if (i < 6) g_score[i] = 0.f;
}

// ---------------- scatter: agg[layer][r][dst] += feat16[src], red.v4.f16x2 ----------------
__global__ void k_scatter(int layer, const int* __restrict__ ei) {
    unsigned idx = blockIdx.x * blockDim.x + threadIdx.x;
    if (idx >= (unsigned)RR * EE * 8u) return;
    const unsigned* src = layer ? g_mixh : g_xh;
    unsigned chunk = idx & 7u;
    unsigned e = idx >> 3;
    unsigned r = e / EE;
    unsigned eo = e - r * EE;
    int s = ei[(size_t)r * 2 * EE + eo];
    int d = ei[(size_t)r * 2 * EE + EE + eo];
    uint4 v = *(const uint4*)(src + (size_t)s * 32 + chunk * 4);
    unsigned* o = g_agg_h + ((size_t)((size_t)layer * RR + r) * NN + d) * 32 + chunk * 4;
    asm volatile("red.global.add.noftz.v4.f16x2 [%0], {%1, %2, %3, %4};"
                 :: "l"(o), "r"(v.x), "r"(v.y), "r"(v.z), "r"(v.w) : "memory");
}

// ---------------- fused layer: conv -> GRU -> attention score ----------------
__global__ __launch_bounds__(256, 2) void k_layer(
    int layer,
    const float* __restrict__ past,
    const float* __restrict__ brel,
    const float* __restrict__ bi, const float* __restrict__ bh,
    const float* __restrict__ kb, const float* __restrict__ q,
    float* __restrict__ cur) {
    extern __shared__ char smem[];
    uint4* sW = (uint4*)smem;                                  // 4608 uint4 paired weights
    unsigned* stage = (unsigned*)(smem + SW_U4 * 16);          // 8 x 576 words
    const int r = blockIdx.y, tid = threadIdx.x;
    const int lane = tid & 31, warp = tid >> 5;
    const int g = lane >> 2, t = lane & 3;
    const int rowA = blockIdx.x * 128 + warp * 16 + g;
    const int rowB = rowA + 8;
    const int nA = min(rowA, NN - 1), nB = min(rowB, NN - 1);
    const unsigned* Ab16 = g_agg_h + (size_t)((size_t)layer * RR + r) * NN * 32;
    const unsigned* Rb16 = layer ? g_mixh : g_xh;
    const float* Pbase = past + (size_t)r * NN * 64;
    unsigned* st = stage + warp * WSTW;

    // ---- cooperative copy of this r's paired weight fragments into SMEM ----
    {
        const uint4* wb = g_wfrag + layer * WL4;
        for (int i = tid; i < SW_U4; i += 256) {
            const uint4* s;
            if (i < 1024)      s = wb + r * 1024 + i;
            else if (i < 4096) s = wb + 3072 + (i - 1024);
            else               s = wb + 6144 + (i - 4096);
            sW[i] = *s;
        }
    }
    __syncthreads();

    // ===== phase A: graphconv -> H (fp16) into stage =====
    {
        unsigned Ah[16], Rh[16];
        load_tile_perm(Ab16, nA, nB, t, Ah);
        load_tile_perm(Rb16, nA, nB, t, Rh);
#pragma unroll
        for (int j = 0; j < 8; j++) {
            float acc0[4] = {}, acc1[4] = {};
#pragma unroll
            for (int ks = 0; ks < 4; ks++) {
                uint4 F = sW[((j * 4 + ks) << 5) + lane];
                mma_h(acc0, Ah + ks * 4, F.x, F.y);
                mma_h(acc1, Rh + ks * 4, F.z, F.w);
            }
            int c0 = j * 8 + 2 * t;
            float2 bb = *(const float2*)(brel + r * 64 + c0);
            int wj = j * 4 + t;
            st[g * STROW + wj] = pack_h2(fmaxf(acc0[0] + acc1[0] + bb.x, 0.f),
                                         fmaxf(acc0[1] + acc1[1] + bb.y, 0.f));
            st[(g + 8) * STROW + wj] = pack_h2(fmaxf(acc0[2] + acc1[2] + bb.x, 0.f),
                                               fmaxf(acc0[3] + acc1[3] + bb.y, 0.f));
        }
    }
    __syncwarp();

    // ===== phase B: GRU; H from stage, past from global; C -> stage =====
    {
        unsigned Hh[16], Ph[16];
#pragma unroll
        for (int ks = 0; ks < 4; ks++) {
            int w0 = ks * 8 + t;
            Hh[ks * 4 + 0] = st[g * STROW + w0];
            Hh[ks * 4 + 1] = st[(g + 8) * STROW + w0];
            Hh[ks * 4 + 2] = st[g * STROW + w0 + 4];
            Hh[ks * 4 + 3] = st[(g + 8) * STROW + w0 + 4];
            load_frag32(Pbase, nA, nB, ks * 16 + 2 * t, Ph + ks * 4);
        }
        __syncwarp();
#pragma unroll
        for (int j = 0; j < 8; j++) {
            // fused accumulators: [0]=r(i+h), [1]=z(i+h), [2]=in, [3]=hn
            float acc[4][4] = {};
#pragma unroll
            for (int ks = 0; ks < 4; ks++) {
                uint4 F0 = sW[S_GRU + 0 * 1024 + ((j * 4 + ks) << 5) + lane];
                mma_h(acc[0], Hh + ks * 4, F0.x, F0.y);
                mma_h(acc[0], Ph + ks * 4, F0.z, F0.w);
                uint4 F1 = sW[S_GRU + 1 * 1024 + ((j * 4 + ks) << 5) + lane];
                mma_h(acc[1], Hh + ks * 4, F1.x, F1.y);
                mma_h(acc[1], Ph + ks * 4, F1.z, F1.w);
                uint4 F2 = sW[S_GRU + 2 * 1024 + ((j * 4 + ks) << 5) + lane];
                mma_h(acc[2], Hh + ks * 4, F2.x, F2.y);
                mma_h(acc[3], Ph + ks * 4, F2.z, F2.w);
            }
            int c0 = j * 8 + 2 * t;
            float2 bir = *(const float2*)(bi + c0);
            float2 biz = *(const float2*)(bi + 64 + c0);
            float2 bin = *(const float2*)(bi + 128 + c0);
            float2 bhr = *(const float2*)(bh + c0);
            float2 bhz = *(const float2*)(bh + 64 + c0);
            float2 bhn = *(const float2*)(bh + 128 + c0);
            float brx = bir.x + bhr.x, bry = bir.y + bhr.y;
            float bzx = biz.x + bhz.x, bzy = biz.y + bhz.y;
            float2 pA = *(const float2*)(Pbase + (size_t)nA * 64 + c0);
            float2 pB = *(const float2*)(Pbase + (size_t)nB * 64 + c0);
            float o[4];
#pragma unroll
            for (int e = 0; e < 4; e++) {
                float bx = (e & 1) ? bry : brx;
                float bz = (e & 1) ? bzy : bzx;
                float bn_i = (e & 1) ? bin.y : bin.x;
                float bn_h = (e & 1) ? bhn.y : bhn.x;
                float p = (e & 2) ? ((e & 1) ? pB.y : pB.x) : ((e & 1) ? pA.y : pA.x);
                float rg = sigmoid_fast(acc[0][e] + bx);
                float zg = sigmoid_fast(acc[1][e] + bz);
                float ng = tanh_fast(acc[2][e] + bn_i + rg * (acc[3][e] + bn_h));
                o[e] = (1.f - zg) * ng + zg * p;
            }
            if (rowA < NN) *(float2*)(cur + ((size_t)r * NN + rowA) * 64 + c0) = make_float2(o[0], o[1]);
            if (rowB < NN) *(float2*)(cur + ((size_t)r * NN + rowB) * 64 + c0) = make_float2(o[2], o[3]);
            int wj = j * 4 + t;
            st[g * STROW + wj] = pack_h2(o[0], o[1]);
            st[(g + 8) * STROW + wj] = pack_h2(o[2], o[3]);
        }
    }
    __syncwarp();

    // ===== phase C: attention score; C from stage (2-way accumulator ILP) =====
    {
        unsigned Ch[16];
#pragma unroll
        for (int ks = 0; ks < 4; ks++) {
            int w0 = ks * 8 + t;
            Ch[ks * 4 + 0] = st[g * STROW + w0];
            Ch[ks * 4 + 1] = st[(g + 8) * STROW + w0];
            Ch[ks * 4 + 2] = st[g * STROW + w0 + 4];
            Ch[ks * 4 + 3] = st[(g + 8) * STROW + w0 + 4];
        }
        float ssum = 0.f;
#pragma unroll
        for (int j = 0; j < 8; j++) {
            float accA[4] = {}, accB[4] = {};
#pragma unroll
            for (int kp = 0; kp < 2; kp++) {
                uint4 F = sW[S_ATT + ((j * 2 + kp) << 5) + lane];
                mma_h(accA, Ch + (2 * kp) * 4, F.x, F.y);
                mma_h(accB, Ch + (2 * kp + 1) * 4, F.z, F.w);
            }
            int c0 = j * 8 + 2 * t;
            float2 kbv = *(const float2*)(kb + c0);
            float2 qv  = *(const float2*)(q + c0);
            if (rowA < NN)
                ssum += qv.x * tanh_fast(accA[0] + accB[0] + kbv.x)
                      + qv.y * tanh_fast(accA[1] + accB[1] + kbv.y);
            if (rowB < NN)
                ssum += qv.x * tanh_fast(accA[2] + accB[2] + kbv.x)
                      + qv.y * tanh_fast(accA[3] + accB[3] + kbv.y);
        }
#pragma unroll
        for (int o = 16; o; o >>= 1) ssum += __shfl_down_sync(0xffffffffu, ssum, o);
        if (lane == 0) atomicAdd(&g_score[layer * 3 + r], ssum);
    }
}

// ---------------- softmax helper (inline, per thread) ----------------
__device__ __forceinline__ void softmax3(int layer, float& a0, float& a1, float& a2) {
    const float inv = 1.0f / (float)NN;
    float s0 = g_score[layer * 3 + 0] * inv;
    float s1 = g_score[layer * 3 + 1] * inv;
    float s2 = g_score[layer * 3 + 2] * inv;
    float m = fmaxf(s0, fmaxf(s1, s2));
    float e0 = __expf(s0 - m), e1 = __expf(s1 - m), e2 = __expf(s2 - m);
    float d = 1.f / (e0 + e1 + e2);
    a0 = e0 * d; a1 = e1 * d; a2 = e2 * d;
}

// ---------------- attention mix (softmax fused): permuted fp16 output ----------------
__global__ void k_mix(const float* __restrict__ cur) {
    int i = blockIdx.x * blockDim.x + threadIdx.x;
    if (i >= NN * 8) return;
    float a0, a1, a2;
    softmax3(0, a0, a1, a2);
    int node = i >> 3, gq = i & 7;
    const float* c0 = cur + (size_t)node * 64;
    const float* c1 = c0 + (size_t)NN * 64;
    const float* c2 = c1 + (size_t)NN * 64;
    unsigned w[4];
#pragma unroll
    for (int u = 0; u < 4; u++) {
        int p = gq * 4 + u;
        int t = p >> 3, ks = (p >> 1) & 3, half = p & 1;
        int col = 2 * (ks * 8 + half * 4 + t);
        float2 v0 = *(const float2*)(c0 + col);
        float2 v1 = *(const float2*)(c1 + col);
        float2 v2 = *(const float2*)(c2 + col);
        w[u] = pack_h2(a0 * v0.x + a1 * v1.x + a2 * v2.x,
                       a0 * v0.y + a1 * v1.y + a2 * v2.y);
    }
    ((uint4*)g_mixh)[i] = make_uint4(w[0], w[1], w[2], w[3]);
}

// ---------------- final projection (softmax fused) ----------------
__global__ __launch_bounds__(128) void k_zfuse(
    const float* __restrict__ cur2, const float* __restrict__ postW,
    const float* __restrict__ postb) {
    int node = blockIdx.x * blockDim.x + threadIdx.x;
    if (node >= NN) return;
    float a0, a1, a2;
    softmax3(1, a0, a1, a2);
    const float4* c0 = (const float4*)(cur2 + (size_t)node * 64);
    const float4* c1 = (const float4*)(cur2 + ((size_t)NN + node) * 64);
    const float4* c2 = (const float4*)(cur2 + ((size_t)2 * NN + node) * 64);
    const float4* w0 = (const float4*)postW;
    const float4* w1 = (const float4*)(postW + 64);
    float z0 = postb[0], z1 = postb[1];
#pragma unroll
    for (int i = 0; i < 16; i++) {
        float4 u0 = c0[i], u1 = c1[i], u2 = c2[i];
        float4 m;
        m.x = a0 * u0.x + a1 * u1.x + a2 * u2.x;
        m.y = a0 * u0.y + a1 * u1.y + a2 * u2.y;
        m.z = a0 * u0.z + a1 * u1.z + a2 * u2.z;
        m.w = a0 * u0.w + a1 * u1.w + a2 * u2.w;
        float4 p0 = w0[i], p1 = w1[i];
        z0 += m.x * p0.x + m.y * p0.y + m.z * p0.z + m.w * p0.w;
        z1 += m.x * p1.x + m.y * p1.y + m.z * p1.z + m.w * p1.w;
    }
    g_z[2 * node] = z0;
    g_z[2 * node + 1] = z1;
}

// ---------------- link scores ----------------
__global__ void k_score(const int* __restrict__ eli, const float* __restrict__ rel,
                        float* __restrict__ scores) {
    int idx = blockIdx.x * blockDim.x + threadIdx.x;
    if (idx >= RR * LL) return;
    int r = idx / LL;
    int l = idx - r * LL;
    int hd = eli[(size_t)r * 2 * LL + l];
    int tl = eli[(size_t)r * 2 * LL + LL + l];
    float hr = g_z[2 * hd], hi = g_z[2 * hd + 1];
    float tr = g_z[2 * tl], ti = g_z[2 * tl + 1];
    float rr = rel[2 * r], ri = rel[2 * r + 1];
    scores[idx] = hr * rr * tr + hi * rr * ti + hr * ri * ti - hi * ri * tr;
}

// ---------------- host ----------------
extern "C" void kernel_launch(void* const* d_in, const int* in_sizes, int n_in,
                              void* d_out, int out_size) {
    const float* x      = (const float*)d_in[0];
    const int*   ei     = (const int*)d_in[1];
    const int*   eli    = (const int*)d_in[2];
    const float* past1  = (const float*)d_in[3];
    const float* past2  = (const float*)d_in[4];
    const float* W1rel  = (const float*)d_in[5];
    const float* b1rel  = (const float*)d_in[6];
    const float* W1root = (const float*)d_in[7];
    const float* g1Wi   = (const float*)d_in[8];
    const float* g1Wh   = (const float*)d_in[9];
    const float* g1bi   = (const float*)d_in[10];
    const float* g1bh   = (const float*)d_in[11];
    const float* k1W    = (const float*)d_in[12];
    const float* k1b    = (const float*)d_in[13];
    const float* q1     = (const float*)d_in[14];
    const float* W2rel  = (const float*)d_in[15];
    const float* b2rel  = (const float*)d_in[16];
    const float* W2root = (const float*)d_in[17];
    const float* g2Wi   = (const float*)d_in[18];
    const float* g2Wh   = (const float*)d_in[19];
    const float* g2bi   = (const float*)d_in[20];
    const float* g2bh   = (const float*)d_in[21];
    const float* k2W    = (const float*)d_in[22];
    const float* k2b    = (const float*)d_in[23];
    const float* q2     = (const float*)d_in[24];
    const float* postW  = (const float*)d_in[25];
    const float* postb  = (const float*)d_in[26];
    const float* relemb = (const float*)d_in[27];

    float* out    = (float*)d_out;
    float* scores = out;
    float* cur1   = out + (size_t)RR * LL;
    float* cur2   = cur1 + (size_t)RR * NN * 64;

    cudaFuncSetAttribute(k_layer, cudaFuncAttributeMaxDynamicSharedMemorySize, SM_TOTAL);

    dim3 gridL((NN + 127) / 128, RR);   // 782 x 3
    const int scat_blocks = (RR * EE * 8 + 255) / 256;

    k_zeroall<<<(2 * RR * NN * 8 + 255) / 256, 256>>>(x);
    k_presplit<<<(2 * WL4 + 255) / 256, 256>>>(
        W1rel, W1root, g1Wi, g1Wh, k1W, W2rel, W2root, g2Wi, g2Wh, k2W);
    k_scatter<<<scat_blocks, 256>>>(0, ei);
    k_layer<<<gridL, 256, SM_TOTAL>>>(0, past1, b1rel, g1bi, g1bh, k1b, q1, cur1);
    k_mix<<<(NN * 8 + 255) / 256, 256>>>(cur1);
    k_scatter<<<scat_blocks, 256>>>(1, ei);   // profiled launch (-s 5 -c 1)
    k_layer<<<gridL, 256, SM_TOTAL>>>(1, past2, b2rel, g2bi, g2bh, k2b, q2, cur2);
    k_zfuse<<<(NN + 127) / 128, 128>>>(cur2, postW, postb);
    k_score<<<(RR * LL + 255) / 256, 256>>>(eli, relemb, scores);
}

// round 16
// speedup vs baseline: 1.2601x; 1.0085x over previous
#include <cuda_runtime.h>
#include <cstdint>

#define NN 100000
#define RR 3
#define EE 800000
#define LL 200000

// ---------------- scratch ----------------
// fp16 tables: 32 f16x2 words per node row, PERMUTED layout:
//   pos = t*8 + ks*2 + half  <->  orig word w = ks*8 + half*4 + t
__device__ __align__(16) unsigned g_agg_h[(size_t)2 * RR * NN * 32];
__device__ __align__(16) unsigned g_xh[(size_t)NN * 32];    // x in fp16 (permuted)
__device__ __align__(16) unsigned g_mixh[(size_t)NN * 32];  // mix in fp16 (permuted)
__device__ __align__(16) float g_z[(size_t)NN * 2];
__device__ float g_score[6];   // [layer*3 + r]

// fp16 weight fragments, PAIRED uint4 layout, per layer WL4 uint4
#define WL4 6656
__device__ __align__(16) uint4 g_wfrag[2 * WL4];

// SMEM (uint4 units): conv slice 1024 @0, gru 3072 @1024, att 512 @4096; then stage
#define S_GRU 1024
#define S_ATT 4096
#define SW_U4 4608                 // 73728 bytes of weights
#define STROW 36
#define WSTW  576                  // stage words per warp (16 rows x 36)
#define SM_TOTAL (SW_U4 * 16 + 8 * WSTW * 4)   // 92160 B

// ---------------- fast math ----------------
__device__ __forceinline__ float tanh_fast(float x) {
    float y;
    asm("tanh.approx.f32 %0, %1;" : "=f"(y) : "f"(x));
    return y;
}
__device__ __forceinline__ float sigmoid_fast(float x) {
    float e = __expf(-x);
    float y;
    asm("rcp.approx.f32 %0, %1;" : "=f"(y) : "f"(1.0f + e));
    return y;
}

// ---------------- fp16 helpers ----------------
__device__ __forceinline__ unsigned pack_h2(float x, float y) {   // lo=x, hi=y
    unsigned d;
    asm("cvt.rn.f16x2.f32 %0, %1, %2;" : "=r"(d) : "f"(y), "f"(x));
    return d;
}
__device__ __forceinline__ void mma_h(float* d, const unsigned* a, unsigned b0, unsigned b1) {
    asm volatile(
        "mma.sync.aligned.m16n8k16.row.col.f32.f16.f16.f32 "
        "{%0,%1,%2,%3},{%4,%5,%6,%7},{%8,%9},{%0,%1,%2,%3};"
        : "+f"(d[0]), "+f"(d[1]), "+f"(d[2]), "+f"(d[3])
        : "r"(a[0]), "r"(a[1]), "r"(a[2]), "r"(a[3]), "r"(b0), "r"(b1));
}
__device__ __forceinline__ void load_tile_perm(const unsigned* tbl, int nA, int nB, int t,
                                               unsigned* f) {
    const uint4* ra = (const uint4*)(tbl + (size_t)nA * 32) + t * 2;
    const uint4* rb = (const uint4*)(tbl + (size_t)nB * 32) + t * 2;
    uint4 a0 = ra[0], a1 = ra[1];
    uint4 b0 = rb[0], b1 = rb[1];
    f[0] = a0.x;  f[2] = a0.y;  f[4] = a0.z;  f[6] = a0.w;
    f[8] = a1.x;  f[10] = a1.y; f[12] = a1.z; f[14] = a1.w;
    f[1] = b0.x;  f[3] = b0.y;  f[5] = b0.z;  f[7] = b0.w;
    f[9] = b1.x;  f[11] = b1.y; f[13] = b1.z; f[15] = b1.w;
}
__device__ __forceinline__ void load_frag32(const float* base, int nA, int nB, int k0,
                                            unsigned* f) {
    float2 v;
    v = *(const float2*)(base + (size_t)nA * 64 + k0);      f[0] = pack_h2(v.x, v.y);
    v = *(const float2*)(base + (size_t)nB * 64 + k0);      f[1] = pack_h2(v.x, v.y);
    v = *(const float2*)(base + (size_t)nA * 64 + k0 + 8);  f[2] = pack_h2(v.x, v.y);
    v = *(const float2*)(base + (size_t)nB * 64 + k0 + 8);  f[3] = pack_h2(v.x, v.y);
}

// ---------------- presplit: build paired uint4 fragment tables ----------------
__global__ void k_presplit(
    const float* __restrict__ w1rel, const float* __restrict__ w1root,
    const float* __restrict__ wi1, const float* __restrict__ wh1,
    const float* __restrict__ kw1,
    const float* __restrict__ w2rel, const float* __restrict__ w2root,
    const float* __restrict__ wi2, const float* __restrict__ wh2,
    const float* __restrict__ kw2) {
    int f = blockIdx.x * blockDim.x + threadIdx.x;
    if (f >= 2 * WL4) return;
    int l = f / WL4;
    int fo = f - l * WL4;
    uint4 out;
    if (fo < 3072) {
        int r = fo >> 10, rem = fo & 1023;
        int j = rem >> 7, ks = (rem >> 5) & 3, lane = rem & 31;
        int g = lane >> 2, t = lane & 3;
        const float* Wr = (l ? w2rel : w1rel) + (size_t)(r * 64 + j * 8 + g) * 64;
        const float* Wo = (l ? w2root : w1root) + (size_t)(r * 64 + j * 8 + g) * 64;
        int k0 = ks * 16 + 2 * t;
        out = make_uint4(pack_h2(Wr[k0], Wr[k0 + 1]), pack_h2(Wr[k0 + 8], Wr[k0 + 9]),
                         pack_h2(Wo[k0], Wo[k0 + 1]), pack_h2(Wo[k0 + 8], Wo[k0 + 9]));
    } else if (fo < 6144) {
        int qq = fo - 3072;
        int m = qq >> 10, rem = qq & 1023;
        int j = rem >> 7, ks = (rem >> 5) & 3, lane = rem & 31;
        int g = lane >> 2, t = lane & 3;
        const float* Wi = (l ? wi2 : wi1) + (size_t)(m * 64 + j * 8 + g) * 64;
        const float* Wh = (l ? wh2 : wh1) + (size_t)(m * 64 + j * 8 + g) * 64;
        int k0 = ks * 16 + 2 * t;
        out = make_uint4(pack_h2(Wi[k0], Wi[k0 + 1]), pack_h2(Wi[k0 + 8], Wi[k0 + 9]),
                         pack_h2(Wh[k0], Wh[k0 + 1]), pack_h2(Wh[k0 + 8], Wh[k0 + 9]));
    } else {
        int qq = fo - 6144;
        int j = qq >> 6, kp = (qq >> 5) & 1, lane = qq & 31;
        int g = lane >> 2, t = lane & 3;
        const float* K = (l ? kw2 : kw1) + (size_t)(j * 8 + g) * 64;
        int ka = (2 * kp) * 16 + 2 * t, kb2 = ka + 16;
        out = make_uint4(pack_h2(K[ka], K[ka + 1]), pack_h2(K[ka + 8], K[ka + 9]),
                         pack_h2(K[kb2], K[kb2 + 1]), pack_h2(K[kb2 + 8], K[kb2 + 9]));
    }
    g_wfrag[f] = out;
}

// ---------------- zero agg (fp16) + convert x -> permuted fp16 + zero scores ----------------
__global__ void k_zeroall(const float* __restrict__ x) {
    int i = blockIdx.x * blockDim.x + threadIdx.x;
    const int totz = 2 * RR * NN * 8;
    if (i < totz) ((uint4*)g_agg_h)[i] = make_uint4(0u, 0u, 0u, 0u);
    if (i < NN * 8) {
        int node = i >> 3, gq = i & 7;
        const float* row = x + (size_t)node * 64;
        unsigned w[4];
#pragma unroll
        for (int u = 0; u < 4; u++) {
            int p = gq * 4 + u;
            int t = p >> 3, ks = (p >> 1) & 3, half = p & 1;
            int wo = ks * 8 + half * 4 + t;
            float2 v = *(const float2*)(row + 2 * wo);
            w[u] = pack_h2(v.x, v.y);
        }
        ((uint4*)g_xh)[i] = make_uint4(w[0], w[1], w[2], w[3]);
    }
    if (i < 6) g_score[i] = 0.f;
}

// ---------------- scatter (single relation r) ----------------
__global__ void k_scatter(int layer, int r, const int* __restrict__ ei) {
    unsigned idx = blockIdx.x * blockDim.x + threadIdx.x;
    if (idx >= (unsigned)EE * 8u) return;
    const unsigned* src = layer ? g_mixh : g_xh;
    unsigned chunk = idx & 7u;
    unsigned eo = idx >> 3;
    int s = ei[(size_t)r * 2 * EE + eo];
    int d = ei[(size_t)r * 2 * EE + EE + eo];
    uint4 v = *(const uint4*)(src + (size_t)s * 32 + chunk * 4);
    unsigned* o = g_agg_h + ((size_t)((size_t)layer * RR + r) * NN + d) * 32 + chunk * 4;
    asm volatile("red.global.add.noftz.v4.f16x2 [%0], {%1, %2, %3, %4};"
                 :: "l"(o), "r"(v.x), "r"(v.y), "r"(v.z), "r"(v.w) : "memory");
}

// ---------------- fused layer (single relation r): conv -> GRU -> attention ----------------
__global__ __launch_bounds__(256, 2) void k_layer(
    int layer, int r,
    const float* __restrict__ past,
    const float* __restrict__ brel,
    const float* __restrict__ bi, const float* __restrict__ bh,
    const float* __restrict__ kb, const float* __restrict__ q,
    float* __restrict__ cur) {
    extern __shared__ char smem[];
    uint4* sW = (uint4*)smem;
    unsigned* stage = (unsigned*)(smem + SW_U4 * 16);
    const int tid = threadIdx.x;
    const int lane = tid & 31, warp = tid >> 5;
    const int g = lane >> 2, t = lane & 3;
    const int rowA = blockIdx.x * 128 + warp * 16 + g;
    const int rowB = rowA + 8;
    const int nA = min(rowA, NN - 1), nB = min(rowB, NN - 1);
    const unsigned* Ab16 = g_agg_h + (size_t)((size_t)layer * RR + r) * NN * 32;
    const unsigned* Rb16 = layer ? g_mixh : g_xh;
    const float* Pbase = past + (size_t)r * NN * 64;
    unsigned* st = stage + warp * WSTW;

    {
        const uint4* wb = g_wfrag + layer * WL4;
        for (int i = tid; i < SW_U4; i += 256) {
            const uint4* s;
            if (i < 1024)      s = wb + r * 1024 + i;
            else if (i < 4096) s = wb + 3072 + (i - 1024);
            else               s = wb + 6144 + (i - 4096);
            sW[i] = *s;
        }
    }
    __syncthreads();

    // ===== phase A: graphconv -> H (fp16) into stage =====
    {
        unsigned Ah[16], Rh[16];
        load_tile_perm(Ab16, nA, nB, t, Ah);
        load_tile_perm(Rb16, nA, nB, t, Rh);
#pragma unroll
        for (int j = 0; j < 8; j++) {
            float acc0[4] = {}, acc1[4] = {};
#pragma unroll
            for (int ks = 0; ks < 4; ks++) {
                uint4 F = sW[((j * 4 + ks) << 5) + lane];
                mma_h(acc0, Ah + ks * 4, F.x, F.y);
                mma_h(acc1, Rh + ks * 4, F.z, F.w);
            }
            int c0 = j * 8 + 2 * t;
            float2 bb = *(const float2*)(brel + r * 64 + c0);
            int wj = j * 4 + t;
            st[g * STROW + wj] = pack_h2(fmaxf(acc0[0] + acc1[0] + bb.x, 0.f),
                                         fmaxf(acc0[1] + acc1[1] + bb.y, 0.f));
            st[(g + 8) * STROW + wj] = pack_h2(fmaxf(acc0[2] + acc1[2] + bb.x, 0.f),
                                               fmaxf(acc0[3] + acc1[3] + bb.y, 0.f));
        }
    }
    __syncwarp();

    // ===== phase B: GRU =====
    {
        unsigned Hh[16], Ph[16];
#pragma unroll
        for (int ks = 0; ks < 4; ks++) {
            int w0 = ks * 8 + t;
            Hh[ks * 4 + 0] = st[g * STROW + w0];
            Hh[ks * 4 + 1] = st[(g + 8) * STROW + w0];
            Hh[ks * 4 + 2] = st[g * STROW + w0 + 4];
            Hh[ks * 4 + 3] = st[(g + 8) * STROW + w0 + 4];
            load_frag32(Pbase, nA, nB, ks * 16 + 2 * t, Ph + ks * 4);
        }
        __syncwarp();
#pragma unroll
        for (int j = 0; j < 8; j++) {
            float acc[4][4] = {};
#pragma unroll
            for (int ks = 0; ks < 4; ks++) {
                uint4 F0 = sW[S_GRU + 0 * 1024 + ((j * 4 + ks) << 5) + lane];
                mma_h(acc[0], Hh + ks * 4, F0.x, F0.y);
                mma_h(acc[0], Ph + ks * 4, F0.z, F0.w);
                uint4 F1 = sW[S_GRU + 1 * 1024 + ((j * 4 + ks) << 5) + lane];
                mma_h(acc[1], Hh + ks * 4, F1.x, F1.y);
                mma_h(acc[1], Ph + ks * 4, F1.z, F1.w);
                uint4 F2 = sW[S_GRU + 2 * 1024 + ((j * 4 + ks) << 5) + lane];
                mma_h(acc[2], Hh + ks * 4, F2.x, F2.y);
                mma_h(acc[3], Ph + ks * 4, F2.z, F2.w);
            }
            int c0 = j * 8 + 2 * t;
            float2 bir = *(const float2*)(bi + c0);
            float2 biz = *(const float2*)(bi + 64 + c0);
            float2 bin = *(const float2*)(bi + 128 + c0);
            float2 bhr = *(const float2*)(bh + c0);
            float2 bhz = *(const float2*)(bh + 64 + c0);
            float2 bhn = *(const float2*)(bh + 128 + c0);
            float brx = bir.x + bhr.x, bry = bir.y + bhr.y;
            float bzx = biz.x + bhz.x, bzy = biz.y + bhz.y;
            float2 pA = *(const float2*)(Pbase + (size_t)nA * 64 + c0);
            float2 pB = *(const float2*)(Pbase + (size_t)nB * 64 + c0);
            float o[4];
#pragma unroll
            for (int e = 0; e < 4; e++) {
                float bx = (e & 1) ? bry : brx;
                float bz = (e & 1) ? bzy : bzx;
                float bn_i = (e & 1) ? bin.y : bin.x;
                float bn_h = (e & 1) ? bhn.y : bhn.x;
                float p = (e & 2) ? ((e & 1) ? pB.y : pB.x) : ((e & 1) ? pA.y : pA.x);
                float rg = sigmoid_fast(acc[0][e] + bx);
                float zg = sigmoid_fast(acc[1][e] + bz);
                float ng = tanh_fast(acc[2][e] + bn_i + rg * (acc[3][e] + bn_h));
                o[e] = (1.f - zg) * ng + zg * p;
            }
            if (rowA < NN) *(float2*)(cur + ((size_t)r * NN + rowA) * 64 + c0) = make_float2(o[0], o[1]);
            if (rowB < NN) *(float2*)(cur + ((size_t)r * NN + rowB) * 64 + c0) = make_float2(o[2], o[3]);
            int wj = j * 4 + t;
            st[g * STROW + wj] = pack_h2(o[0], o[1]);
            st[(g + 8) * STROW + wj] = pack_h2(o[2], o[3]);
        }
    }
    __syncwarp();

    // ===== phase C: attention score =====
    {
        unsigned Ch[16];
#pragma unroll
        for (int ks = 0; ks < 4; ks++) {
            int w0 = ks * 8 + t;
            Ch[ks * 4 + 0] = st[g * STROW + w0];
            Ch[ks * 4 + 1] = st[(g + 8) * STROW + w0];
            Ch[ks * 4 + 2] = st[g * STROW + w0 + 4];
            Ch[ks * 4 + 3] = st[(g + 8) * STROW + w0 + 4];
        }
        float ssum = 0.f;
#pragma unroll
        for (int j = 0; j < 8; j++) {
            float accA[4] = {}, accB[4] = {};
#pragma unroll
            for (int kp = 0; kp < 2; kp++) {
                uint4 F = sW[S_ATT + ((j * 2 + kp) << 5) + lane];
                mma_h(accA, Ch + (2 * kp) * 4, F.x, F.y);
                mma_h(accB, Ch + (2 * kp + 1) * 4, F.z, F.w);
            }
            int c0 = j * 8 + 2 * t;
            float2 kbv = *(const float2*)(kb + c0);
            float2 qv  = *(const float2*)(q + c0);
            if (rowA < NN)
                ssum += qv.x * tanh_fast(accA[0] + accB[0] + kbv.x)
                      + qv.y * tanh_fast(accA[1] + accB[1] + kbv.y);
            if (rowB < NN)
                ssum += qv.x * tanh_fast(accA[2] + accB[2] + kbv.x)
                      + qv.y * tanh_fast(accA[3] + accB[3] + kbv.y);
        }
#pragma unroll
        for (int o = 16; o; o >>= 1) ssum += __shfl_down_sync(0xffffffffu, ssum, o);
        if (lane == 0) atomicAdd(&g_score[layer * 3 + r], ssum);
    }
}

// ---------------- softmax helper ----------------
__device__ __forceinline__ void softmax3(int layer, float& a0, float& a1, float& a2) {
    const float inv = 1.0f / (float)NN;
    float s0 = g_score[layer * 3 + 0] * inv;
    float s1 = g_score[layer * 3 + 1] * inv;
    float s2 = g_score[layer * 3 + 2] * inv;
    float m = fmaxf(s0, fmaxf(s1, s2));
    float e0 = __expf(s0 - m), e1 = __expf(s1 - m), e2 = __expf(s2 - m);
    float d = 1.f / (e0 + e1 + e2);
    a0 = e0 * d; a1 = e1 * d; a2 = e2 * d;
}

// ---------------- attention mix (softmax fused): permuted fp16 output ----------------
__global__ void k_mix(const float* __restrict__ cur) {
    int i = blockIdx.x * blockDim.x + threadIdx.x;
    if (i >= NN * 8) return;
    float a0, a1, a2;
    softmax3(0, a0, a1, a2);
    int node = i >> 3, gq = i & 7;
    const float* c0 = cur + (size_t)node * 64;
    const float* c1 = c0 + (size_t)NN * 64;
    const float* c2 = c1 + (size_t)NN * 64;
    unsigned w[4];
#pragma unroll
    for (int u = 0; u < 4; u++) {
        int p = gq * 4 + u;
        int t = p >> 3, ks = (p >> 1) & 3, half = p & 1;
        int col = 2 * (ks * 8 + half * 4 + t);
        float2 v0 = *(const float2*)(c0 + col);
        float2 v1 = *(const float2*)(c1 + col);
        float2 v2 = *(const float2*)(c2 + col);
        w[u] = pack_h2(a0 * v0.x + a1 * v1.x + a2 * v2.x,
                       a0 * v0.y + a1 * v1.y + a2 * v2.y);
    }
    ((uint4*)g_mixh)[i] = make_uint4(w[0], w[1], w[2], w[3]);
}

// ---------------- final projection (softmax fused) ----------------
__global__ __launch_bounds__(128) void k_zfuse(
    const float* __restrict__ cur2, const float* __restrict__ postW,
    const float* __restrict__ postb) {
    int node = blockIdx.x * blockDim.x + threadIdx.x;
    if (node >= NN) return;
    float a0, a1, a2;
    softmax3(1, a0, a1, a2);
    const float4* c0 = (const float4*)(cur2 + (size_t)node * 64);
    const float4* c1 = (const float4*)(cur2 + ((size_t)NN + node) * 64);
    const float4* c2 = (const float4*)(cur2 + ((size_t)2 * NN + node) * 64);
    const float4* w0 = (const float4*)postW;
    const float4* w1 = (const float4*)(postW + 64);
    float z0 = postb[0], z1 = postb[1];
#pragma unroll
    for (int i = 0; i < 16; i++) {
        float4 u0 = c0[i], u1 = c1[i], u2 = c2[i];
        float4 m;
        m.x = a0 * u0.x + a1 * u1.x + a2 * u2.x;
        m.y = a0 * u0.y + a1 * u1.y + a2 * u2.y;
        m.z = a0 * u0.z + a1 * u1.z + a2 * u2.z;
        m.w = a0 * u0.w + a1 * u1.w + a2 * u2.w;
        float4 p0 = w0[i], p1 = w1[i];
        z0 += m.x * p0.x + m.y * p0.y + m.z * p0.z + m.w * p0.w;
        z1 += m.x * p1.x + m.y * p1.y + m.z * p1.z + m.w * p1.w;
    }
    g_z[2 * node] = z0;
    g_z[2 * node + 1] = z1;
}

// ---------------- link scores ----------------
__global__ void k_score(const int* __restrict__ eli, const float* __restrict__ rel,
                        float* __restrict__ scores) {
    int idx = blockIdx.x * blockDim.x + threadIdx.x;
    if (idx >= RR * LL) return;
    int r = idx / LL;
    int l = idx - r * LL;
    int hd = eli[(size_t)r * 2 * LL + l];
    int tl = eli[(size_t)r * 2 * LL + LL + l];
    float hr = g_z[2 * hd], hi = g_z[2 * hd + 1];
    float tr = g_z[2 * tl], ti = g_z[2 * tl + 1];
    float rr = rel[2 * r], ri = rel[2 * r + 1];
    scores[idx] = hr * rr * tr + hi * rr * ti + hr * ri * ti - hi * ri * tr;
}

// ---------------- host ----------------
extern "C" void kernel_launch(void* const* d_in, const int* in_sizes, int n_in,
                              void* d_out, int out_size) {
    const float* x      = (const float*)d_in[0];
    const int*   ei     = (const int*)d_in[1];
    const int*   eli    = (const int*)d_in[2];
    const float* past1  = (const float*)d_in[3];
    const float* past2  = (const float*)d_in[4];
    const float* W1rel  = (const float*)d_in[5];
    const float* b1rel  = (const float*)d_in[6];
    const float* W1root = (const float*)d_in[7];
    const float* g1Wi   = (const float*)d_in[8];
    const float* g1Wh   = (const float*)d_in[9];
    const float* g1bi   = (const float*)d_in[10];
    const float* g1bh   = (const float*)d_in[11];
    const float* k1W    = (const float*)d_in[12];
    const float* k1b    = (const float*)d_in[13];
    const float* q1     = (const float*)d_in[14];
    const float* W2rel  = (const float*)d_in[15];
    const float* b2rel  = (const float*)d_in[16];
    const float* W2root = (const float*)d_in[17];
    const float* g2Wi   = (const float*)d_in[18];
    const float* g2Wh   = (const float*)d_in[19];
    const float* g2bi   = (const float*)d_in[20];
    const float* g2bh   = (const float*)d_in[21];
    const float* k2W    = (const float*)d_in[22];
    const float* k2b    = (const float*)d_in[23];
    const float* q2     = (const float*)d_in[24];
    const float* postW  = (const float*)d_in[25];
    const float* postb  = (const float*)d_in[26];
    const float* relemb = (const float*)d_in[27];

    float* out    = (float*)d_out;
    float* scores = out;
    float* cur1   = out + (size_t)RR * LL;
    float* cur2   = cur1 + (size_t)RR * NN * 64;

    // persistent side streams/events (host objects; created once, never destroyed)
    static cudaStream_t sr[RR] = {};
    static cudaEvent_t evFork[2] = {}, evJoin[2][RR] = {};
    if (!sr[0]) {
        for (int i = 0; i < RR; i++) cudaStreamCreateWithFlags(&sr[i], cudaStreamNonBlocking);
        for (int l = 0; l < 2; l++) {
            cudaEventCreateWithFlags(&evFork[l], cudaEventDisableTiming);
            for (int i = 0; i < RR; i++)
                cudaEventCreateWithFlags(&evJoin[l][i], cudaEventDisableTiming);
        }
    }

    cudaFuncSetAttribute(k_layer, cudaFuncAttributeMaxDynamicSharedMemorySize, SM_TOTAL);

    const int layer_blocks = (NN + 127) / 128;              // 782
    const int scat_blocks = (EE * 8 + 255) / 256;           // per relation

    const float* pasts[2] = {past1, past2};
    const float* brels[2] = {b1rel, b2rel};
    const float* bis[2]   = {g1bi, g2bi};
    const float* bhs[2]   = {g1bh, g2bh};
    const float* kbs[2]   = {k1b, k2b};
    const float* qs[2]    = {q1, q2};
    float* curs[2]        = {cur1, cur2};

    k_zeroall<<<(2 * RR * NN * 8 + 255) / 256, 256>>>(x);
    k_presplit<<<(2 * WL4 + 255) / 256, 256>>>(
        W1rel, W1root, g1Wi, g1Wh, k1W, W2rel, W2root, g2Wi, g2Wh, k2W);

    for (int l = 0; l < 2; l++) {
        // fork from the main (capture-origin) stream
        cudaEventRecord(evFork[l], 0);
        for (int r = 0; r < RR; r++) {
            cudaStreamWaitEvent(sr[r], evFork[l], 0);
            k_scatter<<<scat_blocks, 256, 0, sr[r]>>>(l, r, ei);
            k_layer<<<layer_blocks, 256, SM_TOTAL, sr[r]>>>(
                l, r, pasts[l], brels[l], bis[l], bhs[l], kbs[l], qs[l], curs[l]);
            cudaEventRecord(evJoin[l][r], sr[r]);
        }
        // join back onto main stream
        for (int r = 0; r < RR; r++) cudaStreamWaitEvent(0, evJoin[l][r], 0);
        if (l == 0) {
            k_mix<<<(NN * 8 + 255) / 256, 256>>>(cur1);
        } else {
            k_zfuse<<<(NN + 127) / 128, 128>>>(cur2, postW, postb);
            k_score<<<(RR * LL + 255) / 256, 256>>>(eli, relemb, scores);
        }
    }
}

// round 17
// speedup vs baseline: 1.2641x; 1.0031x over previous
#include <cuda_runtime.h>
#include <cstdint>

#define NN 100000
#define RR 3
#define EE 800000
#define LL 200000

// ---------------- scratch ----------------
// fp16 tables: 32 f16x2 words per node row, PERMUTED layout:
//   pos = t*8 + ks*2 + half  <->  orig word w = ks*8 + half*4 + t
__device__ __align__(16) unsigned g_agg_h[(size_t)2 * RR * NN * 32];
__device__ __align__(16) unsigned g_xh[(size_t)NN * 32];    // x in fp16 (permuted)
__device__ __align__(16) unsigned g_mixh[(size_t)NN * 32];  // mix in fp16 (permuted)
__device__ __align__(16) float g_z[(size_t)NN * 2];
__device__ float g_score[6];   // [layer*3 + r]

// fp16 weight fragments, PAIRED uint4 layout, per layer WL4 uint4
#define WL4 6656
__device__ __align__(16) uint4 g_wfrag[2 * WL4];
// packed bias tables
__device__ __align__(16) float4 g_bgru[2 * 64];   // {bir+bhr, biz+bhz, bin, bhn}
__device__ __align__(16) float4 g_batt[2 * 32];   // {kb[2p], q[2p], kb[2p+1], q[2p+1]}
__device__ __align__(16) float g_bconv[2 * RR * 64];

// SMEM (uint4 units): conv slice 1024 @0, gru 3072 @1024, att 512 @4096; then stage
#define S_GRU 1024
#define S_ATT 4096
#define SW_U4 4608                 // 73728 bytes of weights
#define STROW 36
#define WSTW  576                  // stage words per warp (16 rows x 36)
#define SM_TOTAL (SW_U4 * 16 + 8 * WSTW * 4)   // 92160 B

// ---------------- fast math ----------------
__device__ __forceinline__ float tanh_fast(float x) {
    float y;
    asm("tanh.approx.f32 %0, %1;" : "=f"(y) : "f"(x));
    return y;
}
__device__ __forceinline__ float sigmoid_fast(float x) {
    float e = __expf(-x);
    float y;
    asm("rcp.approx.f32 %0, %1;" : "=f"(y) : "f"(1.0f + e));
    return y;
}

// ---------------- fp16 helpers ----------------
__device__ __forceinline__ unsigned pack_h2(float x, float y) {   // lo=x, hi=y
    unsigned d;
    asm("cvt.rn.f16x2.f32 %0, %1, %2;" : "=r"(d) : "f"(y), "f"(x));
    return d;
}
__device__ __forceinline__ void unpack_h2(unsigned v, float& x, float& y) {
    asm("{ .reg .b16 l, h; mov.b32 {l, h}, %2; cvt.f32.f16 %0, l; cvt.f32.f16 %1, h; }"
        : "=f"(x), "=f"(y) : "r"(v));
}
__device__ __forceinline__ void mma_h(float* d, const unsigned* a, unsigned b0, unsigned b1) {
    asm volatile(
        "mma.sync.aligned.m16n8k16.row.col.f32.f16.f16.f32 "
        "{%0,%1,%2,%3},{%4,%5,%6,%7},{%8,%9},{%0,%1,%2,%3};"
        : "+f"(d[0]), "+f"(d[1]), "+f"(d[2]), "+f"(d[3])
        : "r"(a[0]), "r"(a[1]), "r"(a[2]), "r"(a[3]), "r"(b0), "r"(b1));
}
__device__ __forceinline__ void load_tile_perm(const unsigned* tbl, int nA, int nB, int t,
                                               unsigned* f) {
    const uint4* ra = (const uint4*)(tbl + (size_t)nA * 32) + t * 2;
    const uint4* rb = (const uint4*)(tbl + (size_t)nB * 32) + t * 2;
    uint4 a0 = ra[0], a1 = ra[1];
    uint4 b0 = rb[0], b1 = rb[1];
    f[0] = a0.x;  f[2] = a0.y;  f[4] = a0.z;  f[6] = a0.w;
    f[8] = a1.x;  f[10] = a1.y; f[12] = a1.z; f[14] = a1.w;
    f[1] = b0.x;  f[3] = b0.y;  f[5] = b0.z;  f[7] = b0.w;
    f[9] = b1.x;  f[11] = b1.y; f[13] = b1.z; f[15] = b1.w;
}
__device__ __forceinline__ void load_frag32(const float* base, int nA, int nB, int k0,
                                            unsigned* f) {
    float2 v;
    v = *(const float2*)(base + (size_t)nA * 64 + k0);      f[0] = pack_h2(v.x, v.y);
    v = *(const float2*)(base + (size_t)nB * 64 + k0);      f[1] = pack_h2(v.x, v.y);
    v = *(const float2*)(base + (size_t)nA * 64 + k0 + 8);  f[2] = pack_h2(v.x, v.y);
    v = *(const float2*)(base + (size_t)nB * 64 + k0 + 8);  f[3] = pack_h2(v.x, v.y);
}

// ---------------- presplit: paired uint4 fragment tables + bias tables ----------------
__global__ void k_presplit(
    const float* __restrict__ w1rel, const float* __restrict__ w1root,
    const float* __restrict__ wi1, const float* __restrict__ wh1,
    const float* __restrict__ kw1,
    const float* __restrict__ w2rel, const float* __restrict__ w2root,
    const float* __restrict__ wi2, const float* __restrict__ wh2,
    const float* __restrict__ kw2,
    const float* __restrict__ b1rel, const float* __restrict__ bi1,
    const float* __restrict__ bh1, const float* __restrict__ kb1,
    const float* __restrict__ q1,
    const float* __restrict__ b2rel, const float* __restrict__ bi2,
    const float* __restrict__ bh2, const float* __restrict__ kb2,
    const float* __restrict__ q2) {
    int f = blockIdx.x * blockDim.x + threadIdx.x;
    if (f >= 2 * WL4 + 576) return;
    if (f >= 2 * WL4) {
        int gx = f - 2 * WL4;
        if (gx < 128) {
            int l = gx >> 6, c = gx & 63;
            const float* bi = l ? bi2 : bi1;
            const float* bh = l ? bh2 : bh1;
            g_bgru[gx] = make_float4(bi[c] + bh[c], bi[64 + c] + bh[64 + c],
                                     bi[128 + c], bh[128 + c]);
        } else if (gx < 192) {
            int gg = gx - 128;
            int l = gg >> 5, p = gg & 31;
            const float* kb = l ? kb2 : kb1;
            const float* q  = l ? q2 : q1;
            g_batt[gg] = make_float4(kb[2 * p], q[2 * p], kb[2 * p + 1], q[2 * p + 1]);
        } else {
            int gg = gx - 192;
            int l = gg / 192, idx = gg - l * 192;
            g_bconv[l * 192 + idx] = (l ? b2rel : b1rel)[idx];
        }
        return;
    }
    int l = f / WL4;
    int fo = f - l * WL4;
    uint4 out;
    if (fo < 3072) {
        int r = fo >> 10, rem = fo & 1023;
        int j = rem >> 7, ks = (rem >> 5) & 3, lane = rem & 31;
        int g = lane >> 2, t = lane & 3;
        const float* Wr = (l ? w2rel : w1rel) + (size_t)(r * 64 + j * 8 + g) * 64;
        const float* Wo = (l ? w2root : w1root) + (size_t)(r * 64 + j * 8 + g) * 64;
        int k0 = ks * 16 + 2 * t;
        out = make_uint4(pack_h2(Wr[k0], Wr[k0 + 1]), pack_h2(Wr[k0 + 8], Wr[k0 + 9]),
                         pack_h2(Wo[k0], Wo[k0 + 1]), pack_h2(Wo[k0 + 8], Wo[k0 + 9]));
    } else if (fo < 6144) {
        int qq = fo - 3072;
        int m = qq >> 10, rem = qq & 1023;
        int j = rem >> 7, ks = (rem >> 5) & 3, lane = rem & 31;
        int g = lane >> 2, t = lane & 3;
        const float* Wi = (l ? wi2 : wi1) + (size_t)(m * 64 + j * 8 + g) * 64;
        const float* Wh = (l ? wh2 : wh1) + (size_t)(m * 64 + j * 8 + g) * 64;
        int k0 = ks * 16 + 2 * t;
        out = make_uint4(pack_h2(Wi[k0], Wi[k0 + 1]), pack_h2(Wi[k0 + 8], Wi[k0 + 9]),
                         pack_h2(Wh[k0], Wh[k0 + 1]), pack_h2(Wh[k0 + 8], Wh[k0 + 9]));
    } else {
        int qq = fo - 6144;
        int j = qq >> 6, kp = (qq >> 5) & 1, lane = qq & 31;
        int g = lane >> 2, t = lane & 3;
        const float* K = (l ? kw2 : kw1) + (size_t)(j * 8 + g) * 64;
        int ka = (2 * kp) * 16 + 2 * t, kb_ = ka + 16;
        out = make_uint4(pack_h2(K[ka], K[ka + 1]), pack_h2(K[ka + 8], K[ka + 9]),
                         pack_h2(K[kb_], K[kb_ + 1]), pack_h2(K[kb_ + 8], K[kb_ + 9]));
    }
    g_wfrag[f] = out;
}

// ---------------- zero agg (fp16) + convert x -> permuted fp16 + zero scores ----------------
__global__ void k_zeroall(const float* __restrict__ x) {
    int i = blockIdx.x * blockDim.x + threadIdx.x;
    const int totz = 2 * RR * NN * 8;
    if (i < totz) ((uint4*)g_agg_h)[i] = make_uint4(0u, 0u, 0u, 0u);
    if (i < NN * 8) {
        int node = i >> 3, gq = i & 7;
        const float* row = x + (size_t)node * 64;
        unsigned w[4];
#pragma unroll
        for (int u = 0; u < 4; u++) {
            int p = gq * 4 + u;
            int t = p >> 3, ks = (p >> 1) & 3, half = p & 1;
            int wo = ks * 8 + half * 4 + t;
            float2 v = *(const float2*)(row + 2 * wo);
            w[u] = pack_h2(v.x, v.y);
        }
        ((uint4*)g_xh)[i] = make_uint4(w[0], w[1], w[2], w[3]);
    }
    if (i < 6) g_score[i] = 0.f;
}

// ---------------- scatter (single relation r) ----------------
__global__ void k_scatter(int layer, int r, const int* __restrict__ ei) {
    unsigned idx = blockIdx.x * blockDim.x + threadIdx.x;
    if (idx >= (unsigned)EE * 8u) return;
    const unsigned* src = layer ? g_mixh : g_xh;
    unsigned chunk = idx & 7u;
    unsigned eo = idx >> 3;
    int s = ei[(size_t)r * 2 * EE + eo];
    int d = ei[(size_t)r * 2 * EE + EE + eo];
    uint4 v = *(const uint4*)(src + (size_t)s * 32 + chunk * 4);
    unsigned* o = g_agg_h + ((size_t)((size_t)layer * RR + r) * NN + d) * 32 + chunk * 4;
    asm volatile("red.global.add.noftz.v4.f16x2 [%0], {%1, %2, %3, %4};"
                 :: "l"(o), "r"(v.x), "r"(v.y), "r"(v.z), "r"(v.w) : "memory");
}

// ---------------- fused layer (single relation r): conv -> GRU -> attention ----------------
__global__ __launch_bounds__(256, 2) void k_layer(
    int layer, int r,
    const float* __restrict__ past,
    float* __restrict__ cur) {
    extern __shared__ char smem[];
    uint4* sW = (uint4*)smem;
    unsigned* stage = (unsigned*)(smem + SW_U4 * 16);
    const int tid = threadIdx.x;
    const int lane = tid & 31, warp = tid >> 5;
    const int g = lane >> 2, t = lane & 3;
    const int rowA = blockIdx.x * 128 + warp * 16 + g;
    const int rowB = rowA + 8;
    const int nA = min(rowA, NN - 1), nB = min(rowB, NN - 1);
    const unsigned* Ab16 = g_agg_h + (size_t)((size_t)layer * RR + r) * NN * 32;
    const unsigned* Rb16 = layer ? g_mixh : g_xh;
    const float* Pbase = past + (size_t)r * NN * 64;
    unsigned* st = stage + warp * WSTW;

    {
        const uint4* wb = g_wfrag + layer * WL4;
        for (int i = tid; i < SW_U4; i += 256) {
            const uint4* s;
            if (i < 1024)      s = wb + r * 1024 + i;
            else if (i < 4096) s = wb + 3072 + (i - 1024);
            else               s = wb + 6144 + (i - 4096);
            sW[i] = *s;
        }
    }
    __syncthreads();

    // ===== phase A: graphconv -> H (fp16) into stage =====
    {
        unsigned Ah[16], Rh[16];
        load_tile_perm(Ab16, nA, nB, t, Ah);
        load_tile_perm(Rb16, nA, nB, t, Rh);
#pragma unroll
        for (int j = 0; j < 8; j++) {
            float acc0[4] = {}, acc1[4] = {};
#pragma unroll
            for (int ks = 0; ks < 4; ks++) {
                uint4 F = sW[((j * 4 + ks) << 5) + lane];
                mma_h(acc0, Ah + ks * 4, F.x, F.y);
                mma_h(acc1, Rh + ks * 4, F.z, F.w);
            }
            int c0 = j * 8 + 2 * t;
            float2 bb = *(const float2*)(g_bconv + (layer * RR + r) * 64 + c0);
            int wj = j * 4 + t;
            st[g * STROW + wj] = pack_h2(fmaxf(acc0[0] + acc1[0] + bb.x, 0.f),
                                         fmaxf(acc0[1] + acc1[1] + bb.y, 0.f));
            st[(g + 8) * STROW + wj] = pack_h2(fmaxf(acc0[2] + acc1[2] + bb.x, 0.f),
                                               fmaxf(acc0[3] + acc1[3] + bb.y, 0.f));
        }
    }
    __syncwarp();

    // ===== phase B: GRU =====
    {
        unsigned Hh[16], Ph[16];
#pragma unroll
        for (int ks = 0; ks < 4; ks++) {
            int w0 = ks * 8 + t;
            Hh[ks * 4 + 0] = st[g * STROW + w0];
            Hh[ks * 4 + 1] = st[(g + 8) * STROW + w0];
            Hh[ks * 4 + 2] = st[g * STROW + w0 + 4];
            Hh[ks * 4 + 3] = st[(g + 8) * STROW + w0 + 4];
            load_frag32(Pbase, nA, nB, ks * 16 + 2 * t, Ph + ks * 4);
        }
        __syncwarp();
#pragma unroll
        for (int j = 0; j < 8; j++) {
            float acc[4][4] = {};
#pragma unroll
            for (int ks = 0; ks < 4; ks++) {
                uint4 F0 = sW[S_GRU + 0 * 1024 + ((j * 4 + ks) << 5) + lane];
                mma_h(acc[0], Hh + ks * 4, F0.x, F0.y);
                mma_h(acc[0], Ph + ks * 4, F0.z, F0.w);
                uint4 F1 = sW[S_GRU + 1 * 1024 + ((j * 4 + ks) << 5) + lane];
                mma_h(acc[1], Hh + ks * 4, F1.x, F1.y);
                mma_h(acc[1], Ph + ks * 4, F1.z, F1.w);
                uint4 F2 = sW[S_GRU + 2 * 1024 + ((j * 4 + ks) << 5) + lane];
                mma_h(acc[2], Hh + ks * 4, F2.x, F2.y);
                mma_h(acc[3], Ph + ks * 4, F2.z, F2.w);
            }
            int c0 = j * 8 + 2 * t;
            float4 b0 = g_bgru[layer * 64 + c0];
            float4 b1 = g_bgru[layer * 64 + c0 + 1];
            // past pair (c0, c0+1) from Ph fragments (fp16-rounded)
            float pAx, pAy, pBx, pBy;
            int pw = (j >> 1) * 4 + (j & 1) * 2;
            unpack_h2(Ph[pw],     pAx, pAy);
            unpack_h2(Ph[pw + 1], pBx, pBy);
            float o[4];
#pragma unroll
            for (int e = 0; e < 4; e++) {
                const float4& bb = (e & 1) ? b1 : b0;
                float p = (e & 2) ? ((e & 1) ? pBy : pBx) : ((e & 1) ? pAy : pAx);
                float rg = sigmoid_fast(acc[0][e] + bb.x);
                float zg = sigmoid_fast(acc[1][e] + bb.y);
                float ng = tanh_fast(acc[2][e] + bb.z + rg * (acc[3][e] + bb.w));
                o[e] = (1.f - zg) * ng + zg * p;
            }
            if (rowA < NN) *(float2*)(cur + ((size_t)r * NN + rowA) * 64 + c0) = make_float2(o[0], o[1]);
            if (rowB < NN) *(float2*)(cur + ((size_t)r * NN + rowB) * 64 + c0) = make_float2(o[2], o[3]);
            int wj = j * 4 + t;
            st[g * STROW + wj] = pack_h2(o[0], o[1]);
            st[(g + 8) * STROW + wj] = pack_h2(o[2], o[3]);
        }
    }
    __syncwarp();

    // ===== phase C: attention score =====
    {
        unsigned Ch[16];
#pragma unroll
        for (int ks = 0; ks < 4; ks++) {
            int w0 = ks * 8 + t;
            Ch[ks * 4 + 0] = st[g * STROW + w0];
            Ch[ks * 4 + 1] = st[(g + 8) * STROW + w0];
            Ch[ks * 4 + 2] = st[g * STROW + w0 + 4];
            Ch[ks * 4 + 3] = st[(g + 8) * STROW + w0 + 4];
        }
        float ssum = 0.f;
#pragma unroll
        for (int j = 0; j < 8; j++) {
            float accA[4] = {}, accB[4] = {};
#pragma unroll
            for (int kp = 0; kp < 2; kp++) {
                uint4 F = sW[S_ATT + ((j * 2 + kp) << 5) + lane];
                mma_h(accA, Ch + (2 * kp) * 4, F.x, F.y);
                mma_h(accB, Ch + (2 * kp + 1) * 4, F.z, F.w);
            }
            float4 kq = g_batt[layer * 32 + j * 4 + t];   // {kb0,q0,kb1,q1}
            if (rowA < NN)
                ssum += kq.y * tanh_fast(accA[0] + accB[0] + kq.x)
                      + kq.w * tanh_fast(accA[1] + accB[1] + kq.z);
            if (rowB < NN)
                ssum += kq.y * tanh_fast(accA[2] + accB[2] + kq.x)
                      + kq.w * tanh_fast(accA[3] + accB[3] + kq.z);
        }
#pragma unroll
        for (int o = 16; o; o >>= 1) ssum += __shfl_down_sync(0xffffffffu, ssum, o);
        if (lane == 0) atomicAdd(&g_score[layer * 3 + r], ssum);
    }
}

// ---------------- softmax helper ----------------
__device__ __forceinline__ void softmax3(int layer, float& a0, float& a1, float& a2) {
    const float inv = 1.0f / (float)NN;
    float s0 = g_score[layer * 3 + 0] * inv;
    float s1 = g_score[layer * 3 + 1] * inv;
    float s2 = g_score[layer * 3 + 2] * inv;
    float m = fmaxf(s0, fmaxf(s1, s2));
    float e0 = __expf(s0 - m), e1 = __expf(s1 - m), e2 = __expf(s2 - m);
    float d = 1.f / (e0 + e1 + e2);
    a0 = e0 * d; a1 = e1 * d; a2 = e2 * d;
}

// ---------------- attention mix (softmax fused): permuted fp16 output ----------------
__global__ void k_mix(const float* __restrict__ cur) {
    int i = blockIdx.x * blockDim.x + threadIdx.x;
    if (i >= NN * 8) return;
    float a0, a1, a2;
    softmax3(0, a0, a1, a2);
    int node = i >> 3, gq = i & 7;
    const float* c0 = cur + (size_t)node * 64;
    const float* c1 = c0 + (size_t)NN * 64;
    const float* c2 = c1 + (size_t)NN * 64;
    unsigned w[4];
#pragma unroll
    for (int u = 0; u < 4; u++) {
        int p = gq * 4 + u;
        int t = p >> 3, ks = (p >> 1) & 3, half = p & 1;
        int col = 2 * (ks * 8 + half * 4 + t);
        float2 v0 = *(const float2*)(c0 + col);
        float2 v1 = *(const float2*)(c1 + col);
        float2 v2 = *(const float2*)(c2 + col);
        w[u] = pack_h2(a0 * v0.x + a1 * v1.x + a2 * v2.x,
                       a0 * v0.y + a1 * v1.y + a2 * v2.y);
    }
    ((uint4*)g_mixh)[i] = make_uint4(w[0], w[1], w[2], w[3]);
}

// ---------------- final projection (softmax fused) ----------------
__global__ __launch_bounds__(128) void k_zfuse(
    const float* __restrict__ cur2, const float* __restrict__ postW,
    const float* __restrict__ postb) {
    int node = blockIdx.x * blockDim.x + threadIdx.x;
    if (node >= NN) return;
    float a0, a1, a2;
    softmax3(1, a0, a1, a2);
    const float4* c0 = (const float4*)(cur2 + (size_t)node * 64);
    const float4* c1 = (const float4*)(cur2 + ((size_t)NN + node) * 64);
    const float4* c2 = (const float4*)(cur2 + ((size_t)2 * NN + node) * 64);
    const float4* w0 = (const float4*)postW;
    const float4* w1 = (const float4*)(postW + 64);
    float z0 = postb[0], z1 = postb[1];
#pragma unroll
    for (int i = 0; i < 16; i++) {
        float4 u0 = c0[i], u1 = c1[i], u2 = c2[i];
        float4 m;
        m.x = a0 * u0.x + a1 * u1.x + a2 * u2.x;
        m.y = a0 * u0.y + a1 * u1.y + a2 * u2.y;
        m.z = a0 * u0.z + a1 * u1.z + a2 * u2.z;
        m.w = a0 * u0.w + a1 * u1.w + a2 * u2.w;
        float4 p0 = w0[i], p1 = w1[i];
        z0 += m.x * p0.x + m.y * p0.y + m.z * p0.z + m.w * p0.w;
        z1 += m.x * p1.x + m.y * p1.y + m.z * p1.z + m.w * p1.w;
    }
    g_z[2 * node] = z0;
    g_z[2 * node + 1] = z1;
}

// ---------------- link scores ----------------
__global__ void k_score(const int* __restrict__ eli, const float* __restrict__ rel,
                        float* __restrict__ scores) {
    int idx = blockIdx.x * blockDim.x + threadIdx.x;
    if (idx >= RR * LL) return;
    int r = idx / LL;
    int l = idx - r * LL;
    int hd = eli[(size_t)r * 2 * LL + l];
    int tl = eli[(size_t)r * 2 * LL + LL + l];
    float hr = g_z[2 * hd], hi = g_z[2 * hd + 1];
    float tr = g_z[2 * tl], ti = g_z[2 * tl + 1];
    float rr = rel[2 * r], ri = rel[2 * r + 1];
    scores[idx] = hr * rr * tr + hi * rr * ti + hr * ri * ti - hi * ri * tr;
}

// ---------------- host ----------------
extern "C" void kernel_launch(void* const* d_in, const int* in_sizes, int n_in,
                              void* d_out, int out_size) {
    const float* x      = (const float*)d_in[0];
    const int*   ei     = (const int*)d_in[1];
    const int*   eli    = (const int*)d_in[2];
    const float* past1  = (const float*)d_in[3];
    const float* past2  = (const float*)d_in[4];
    const float* W1rel  = (const float*)d_in[5];
    const float* b1rel  = (const float*)d_in[6];
    const float* W1root = (const float*)d_in[7];
    const float* g1Wi   = (const float*)d_in[8];
    const float* g1Wh   = (const float*)d_in[9];
    const float* g1bi   = (const float*)d_in[10];
    const float* g1bh   = (const float*)d_in[11];
    const float* k1W    = (const float*)d_in[12];
    const float* k1b    = (const float*)d_in[13];
    const float* q1     = (const float*)d_in[14];
    const float* W2rel  = (const float*)d_in[15];
    const float* b2rel  = (const float*)d_in[16];
    const float* W2root = (const float*)d_in[17];
    const float* g2Wi   = (const float*)d_in[18];
    const float* g2Wh   = (const float*)d_in[19];
    const float* g2bi   = (const float*)d_in[20];
    const float* g2bh   = (const float*)d_in[21];
    const float* k2W    = (const float*)d_in[22];
    const float* k2b    = (const float*)d_in[23];
    const float* q2     = (const float*)d_in[24];
    const float* postW  = (const float*)d_in[25];
    const float* postb  = (const float*)d_in[26];
    const float* relemb = (const float*)d_in[27];

    float* out    = (float*)d_out;
    float* scores = out;
    float* cur1   = out + (size_t)RR * LL;
    float* cur2   = cur1 + (size_t)RR * NN * 64;

    static cudaStream_t sr[RR] = {};
    static cudaEvent_t evFork[2] = {}, evJoin[2][RR] = {};
    if (!sr[0]) {
        for (int i = 0; i < RR; i++) cudaStreamCreateWithFlags(&sr[i], cudaStreamNonBlocking);
        for (int l = 0; l < 2; l++) {
            cudaEventCreateWithFlags(&evFork[l], cudaEventDisableTiming);
            for (int i = 0; i < RR; i++)
                cudaEventCreateWithFlags(&evJoin[l][i], cudaEventDisableTiming);
        }
    }

    cudaFuncSetAttribute(k_layer, cudaFuncAttributeMaxDynamicSharedMemorySize, SM_TOTAL);

    const int layer_blocks = (NN + 127) / 128;              // 782
    const int scat_blocks = (EE * 8 + 255) / 256;           // per relation

    const float* pasts[2] = {past1, past2};
    float* curs[2]        = {cur1, cur2};

    k_zeroall<<<(2 * RR * NN * 8 + 255) / 256, 256>>>(x);
    k_presplit<<<(2 * WL4 + 576 + 255) / 256, 256>>>(
        W1rel, W1root, g1Wi, g1Wh, k1W, W2rel, W2root, g2Wi, g2Wh, k2W,
        b1rel, g1bi, g1bh, k1b, q1, b2rel, g2bi, g2bh, k2b, q2);

    for (int l = 0; l < 2; l++) {
        cudaEventRecord(evFork[l], 0);
        for (int r = 0; r < RR; r++) {
            cudaStreamWaitEvent(sr[r], evFork[l], 0);
            k_scatter<<<scat_blocks, 256, 0, sr[r]>>>(l, r, ei);
            k_layer<<<layer_blocks, 256, SM_TOTAL, sr[r]>>>(l, r, pasts[l], curs[l]);
            cudaEventRecord(evJoin[l][r], sr[r]);
        }
        for (int r = 0; r < RR; r++) cudaStreamWaitEvent(0, evJoin[l][r], 0);
        if (l == 0) {
            k_mix<<<(NN * 8 + 255) / 256, 256>>>(cur1);
        } else {
            k_zfuse<<<(NN + 127) / 128, 128>>>(cur2, postW, postb);
            k_score<<<(RR * LL + 255) / 256, 256>>>(eli, relemb, scores);
        }
    }
}